// round 1
// baseline (speedup 1.0000x reference)
#include <cuda_runtime.h>
#include <math.h>

#define B_  2
#define S_  2048
#define D_  2048
#define H_  16
#define HD_ 128
#define M_  (B_*S_)   // 4096 rows

// ---------------- scratch (static device globals; allocation-free) ----------
__device__ float g_h  [(size_t)M_*D_];
__device__ float g_q  [(size_t)M_*D_];
__device__ float g_k  [(size_t)M_*D_];
__device__ float g_v  [(size_t)M_*D_];
__device__ float g_x2 [(size_t)M_*D_];
__device__ float g_r  [(size_t)M_*D_];
__device__ float g_h3 [(size_t)M_*D_];
__device__ float g_t  [(size_t)M_*4*D_];   // big: FFN 2D / MLP 4D intermediates + attn out
__device__ float g_pers[D_];

// ---------------- GEMM: C = [gelu](A @ W + bias) [+ res] --------------------
// A: MxK row-major, W: KxN row-major. M,N % 128 == 0, K % 16 == 0 (true here).
template<bool GELU, bool BIAS, bool RES>
__global__ __launch_bounds__(256)
void gemm_kernel(const float* __restrict__ A, const float* __restrict__ W,
                 const float* __restrict__ bias, const float* __restrict__ res,
                 float* __restrict__ C, int M, int N, int K)
{
    __shared__ float As[16*132];   // transposed A tile, padded stride
    __shared__ float Bs[16*128];
    const int tid = threadIdx.x;
    const int m0 = blockIdx.y * 128, n0 = blockIdx.x * 128;
    const int tm = tid >> 4, tn = tid & 15;

    float acc[8][8];
    #pragma unroll
    for (int i = 0; i < 8; i++)
        #pragma unroll
        for (int j = 0; j < 8; j++) acc[i][j] = 0.f;

    for (int k0 = 0; k0 < K; k0 += 16) {
        #pragma unroll
        for (int li = 0; li < 2; ++li) {
            int v = li*256 + tid;
            int m = v >> 2, kq = (v & 3) * 4;
            float4 a = *(const float4*)&A[(size_t)(m0+m)*K + k0 + kq];
            As[(kq+0)*132+m] = a.x; As[(kq+1)*132+m] = a.y;
            As[(kq+2)*132+m] = a.z; As[(kq+3)*132+m] = a.w;
        }
        #pragma unroll
        for (int li = 0; li < 2; ++li) {
            int v = li*256 + tid;
            int k = v >> 5, nq = (v & 31) * 4;
            *(float4*)&Bs[k*128+nq] = *(const float4*)&W[(size_t)(k0+k)*N + n0 + nq];
        }
        __syncthreads();
        #pragma unroll
        for (int k = 0; k < 16; k++) {
            float a[8], b[8];
            *(float4*)&a[0] = *(float4*)&As[k*132 + tm*8];
            *(float4*)&a[4] = *(float4*)&As[k*132 + tm*8 + 4];
            *(float4*)&b[0] = *(float4*)&Bs[k*128 + tn*8];
            *(float4*)&b[4] = *(float4*)&Bs[k*128 + tn*8 + 4];
            #pragma unroll
            for (int i = 0; i < 8; i++)
                #pragma unroll
                for (int j = 0; j < 8; j++)
                    acc[i][j] = fmaf(a[i], b[j], acc[i][j]);
        }
        __syncthreads();
    }

    float bv[8];
    if (BIAS) {
        *(float4*)&bv[0] = *(const float4*)&bias[n0 + tn*8];
        *(float4*)&bv[4] = *(const float4*)&bias[n0 + tn*8 + 4];
    }
    #pragma unroll
    for (int i = 0; i < 8; i++) {
        size_t off = (size_t)(m0 + tm*8 + i)*N + n0 + tn*8;
        float o[8];
        #pragma unroll
        for (int j = 0; j < 8; j++) {
            float x = acc[i][j];
            if (BIAS) x += bv[j];
            if (GELU) x = 0.5f * x * (1.0f + erff(x * 0.70710678118654752f));
            o[j] = x;
        }
        if (RES) {
            float4 r0 = *(const float4*)&res[off];
            float4 r1 = *(const float4*)&res[off+4];
            o[0]+=r0.x; o[1]+=r0.y; o[2]+=r0.z; o[3]+=r0.w;
            o[4]+=r1.x; o[5]+=r1.y; o[6]+=r1.z; o[7]+=r1.w;
        }
        *(float4*)&C[off]   = make_float4(o[0],o[1],o[2],o[3]);
        *(float4*)&C[off+4] = make_float4(o[4],o[5],o[6],o[7]);
    }
}

// ---------------- LayerNorm: out = LN(A [+ Ad]) * g + b ---------------------
__global__ __launch_bounds__(256)
void ln_kernel(const float* __restrict__ A, const float* __restrict__ Ad,
               const float* __restrict__ g, const float* __restrict__ bb,
               float* __restrict__ out)
{
    const int row = blockIdx.x, t = threadIdx.x;
    const float* a = A + (size_t)row * D_;
    float4 v[2];
    float s = 0.f, ss = 0.f;
    #pragma unroll
    for (int i = 0; i < 2; i++) {
        int idx = (i*256 + t) * 4;
        float4 x = *(const float4*)&a[idx];
        if (Ad) {
            float4 y = *(const float4*)&Ad[(size_t)row*D_ + idx];
            x.x += y.x; x.y += y.y; x.z += y.z; x.w += y.w;
        }
        v[i] = x;
        s  += x.x + x.y + x.z + x.w;
        ss += x.x*x.x + x.y*x.y + x.z*x.z + x.w*x.w;
    }
    #pragma unroll
    for (int off = 16; off; off >>= 1) {
        s  += __shfl_xor_sync(0xffffffffu, s,  off);
        ss += __shfl_xor_sync(0xffffffffu, ss, off);
    }
    __shared__ float sb[8], ssb[8];
    if ((t & 31) == 0) { sb[t>>5] = s; ssb[t>>5] = ss; }
    __syncthreads();
    float st = 0.f, sst = 0.f;
    #pragma unroll
    for (int i = 0; i < 8; i++) { st += sb[i]; sst += ssb[i]; }
    float mean = st * (1.f / D_);
    float var  = sst * (1.f / D_) - mean * mean;
    float rstd = rsqrtf(var + 1e-5f);
    #pragma unroll
    for (int i = 0; i < 2; i++) {
        int idx = (i*256 + t) * 4;
        float4 gg  = *(const float4*)&g[idx];
        float4 bbv = *(const float4*)&bb[idx];
        float4 x = v[i], o;
        o.x = (x.x - mean)*rstd*gg.x + bbv.x;
        o.y = (x.y - mean)*rstd*gg.y + bbv.y;
        o.z = (x.z - mean)*rstd*gg.z + bbv.z;
        o.w = (x.w - mean)*rstd*gg.w + bbv.w;
        *(float4*)&out[(size_t)row*D_ + idx] = o;
    }
}

// ---------------- persona vector: pers[j] = pemb[t]@dw[D:2D, j] + db[j] -----
__global__ __launch_bounds__(256)
void pers_kernel(const float* __restrict__ pemb, const int* __restrict__ trait,
                 const float* __restrict__ dw, const float* __restrict__ db,
                 float* __restrict__ out)
{
    int j = blockIdx.x * 256 + threadIdx.x;
    int t = trait[0];
    const float* pe = pemb + (size_t)t * D_;
    float acc = db[j];
    for (int i = 0; i < D_; ++i)
        acc = fmaf(pe[i], dw[(size_t)(D_ + i) * D_ + j], acc);
    out[j] = acc;
}

// ---------------- flash attention (fp32, online softmax) --------------------
// Q,K,V stored [B,S,D] with head h at cols h*128..h*128+127. O same layout.
// Block: 64 queries x full head. Tiles of 64 keys. 256 threads = 16x16 map,
// each thread owns 4 q-rows x 4 k-cols for scores, 4 q-rows x 8 dims for O.
__global__ __launch_bounds__(256)
void attn_kernel(const float* __restrict__ Q, const float* __restrict__ K,
                 const float* __restrict__ V, const int* __restrict__ mask,
                 float* __restrict__ O)
{
    extern __shared__ float sm[];
    float* Qt = sm;           // [128][64]  (d-major, conflict-free frags)
    float* Kt = sm + 8192;    // [128][64]
    float* Vs = sm + 16384;   // [64][128]
    float* Ps = sm + 24576;   // [64][64]
    const int tid = threadIdx.x;
    const int b = blockIdx.z, h = blockIdx.y;
    const int q0 = blockIdx.x * 64;
    const float scale = 0.088388347648318447f;  // 1/sqrt(128)

    #pragma unroll
    for (int it = 0; it < 8; ++it) {
        int e = (it*256 + tid) * 4;
        int row = e >> 7, d = e & 127;
        float4 qv = *(const float4*)&Q[((size_t)(b*S_ + q0 + row))*D_ + h*HD_ + d];
        Qt[(d+0)*64+row] = qv.x*scale; Qt[(d+1)*64+row] = qv.y*scale;
        Qt[(d+2)*64+row] = qv.z*scale; Qt[(d+3)*64+row] = qv.w*scale;
    }

    const int ty = tid >> 4, tx = tid & 15;
    float m_i[4], l_i[4], acc[4][8];
    #pragma unroll
    for (int i = 0; i < 4; i++) {
        m_i[i] = -1e30f; l_i[i] = 0.f;
        #pragma unroll
        for (int dd = 0; dd < 8; dd++) acc[i][dd] = 0.f;
    }

    for (int k0 = 0; k0 < S_; k0 += 64) {
        __syncthreads();
        #pragma unroll
        for (int it = 0; it < 8; ++it) {
            int e = (it*256 + tid) * 4;
            int row = e >> 7, d = e & 127;
            size_t goff = ((size_t)(b*S_ + k0 + row))*D_ + h*HD_ + d;
            float4 kv = *(const float4*)&K[goff];
            Kt[(d+0)*64+row] = kv.x; Kt[(d+1)*64+row] = kv.y;
            Kt[(d+2)*64+row] = kv.z; Kt[(d+3)*64+row] = kv.w;
            *(float4*)&Vs[row*128 + d] = *(const float4*)&V[goff];
        }
        __syncthreads();

        float s[4][4];
        #pragma unroll
        for (int i = 0; i < 4; i++)
            #pragma unroll
            for (int j = 0; j < 4; j++) s[i][j] = 0.f;
        #pragma unroll 4
        for (int d = 0; d < 128; ++d) {
            float4 qv = *(float4*)&Qt[d*64 + ty*4];
            float4 kv = *(float4*)&Kt[d*64 + tx*4];
            float qa[4] = {qv.x, qv.y, qv.z, qv.w};
            float ka[4] = {kv.x, kv.y, kv.z, kv.w};
            #pragma unroll
            for (int i = 0; i < 4; i++)
                #pragma unroll
                for (int j = 0; j < 4; j++)
                    s[i][j] = fmaf(qa[i], ka[j], s[i][j]);
        }
        // mask (where mask==0 -> -inf before softmax)
        #pragma unroll
        for (int j = 0; j < 4; j++) {
            if (mask[b*S_ + k0 + tx*4 + j] == 0) {
                #pragma unroll
                for (int i = 0; i < 4; i++) s[i][j] = -1e30f;
            }
        }
        // online softmax update
        #pragma unroll
        for (int i = 0; i < 4; i++) {
            float rm = fmaxf(fmaxf(s[i][0], s[i][1]), fmaxf(s[i][2], s[i][3]));
            rm = fmaxf(rm, __shfl_xor_sync(0xffffffffu, rm, 8, 16));
            rm = fmaxf(rm, __shfl_xor_sync(0xffffffffu, rm, 4, 16));
            rm = fmaxf(rm, __shfl_xor_sync(0xffffffffu, rm, 2, 16));
            rm = fmaxf(rm, __shfl_xor_sync(0xffffffffu, rm, 1, 16));
            float m_new = fmaxf(m_i[i], rm);
            float corr  = __expf(m_i[i] - m_new);
            float p[4], rs = 0.f;
            #pragma unroll
            for (int j = 0; j < 4; j++) { p[j] = __expf(s[i][j] - m_new); rs += p[j]; }
            rs += __shfl_xor_sync(0xffffffffu, rs, 8, 16);
            rs += __shfl_xor_sync(0xffffffffu, rs, 4, 16);
            rs += __shfl_xor_sync(0xffffffffu, rs, 2, 16);
            rs += __shfl_xor_sync(0xffffffffu, rs, 1, 16);
            l_i[i] = l_i[i]*corr + rs;
            m_i[i] = m_new;
            #pragma unroll
            for (int dd = 0; dd < 8; dd++) acc[i][dd] *= corr;
            *(float4*)&Ps[(ty*4 + i)*64 + tx*4] = make_float4(p[0], p[1], p[2], p[3]);
        }
        __syncthreads();
        // O += P @ V
        #pragma unroll 4
        for (int j = 0; j < 64; ++j) {
            float4 v0 = *(float4*)&Vs[j*128 + tx*8];
            float4 v1 = *(float4*)&Vs[j*128 + tx*8 + 4];
            float vv[8] = {v0.x, v0.y, v0.z, v0.w, v1.x, v1.y, v1.z, v1.w};
            #pragma unroll
            for (int i = 0; i < 4; i++) {
                float pv = Ps[(ty*4 + i)*64 + j];
                #pragma unroll
                for (int dd = 0; dd < 8; dd++)
                    acc[i][dd] = fmaf(pv, vv[dd], acc[i][dd]);
            }
        }
    }
    #pragma unroll
    for (int i = 0; i < 4; i++) {
        float inv = 1.0f / l_i[i];
        size_t off = ((size_t)(b*S_ + q0 + ty*4 + i))*D_ + h*HD_ + tx*8;
        *(float4*)&O[off]   = make_float4(acc[i][0]*inv, acc[i][1]*inv, acc[i][2]*inv, acc[i][3]*inv);
        *(float4*)&O[off+4] = make_float4(acc[i][4]*inv, acc[i][5]*inv, acc[i][6]*inv, acc[i][7]*inv);
    }
}

// ---------------- launch ----------------------------------------------------
extern "C" void kernel_launch(void* const* d_in, const int* in_sizes, int n_in,
                              void* d_out, int out_size)
{
    const float* x     = (const float*)d_in[0];
    const int*   mask  = (const int*)  d_in[1];
    const int*   trait = (const int*)  d_in[2];
    const float* wq    = (const float*)d_in[3];
    const float* wk    = (const float*)d_in[4];
    const float* wv    = (const float*)d_in[5];
    const float* wo    = (const float*)d_in[6];
    const float* g1    = (const float*)d_in[7];
    const float* b1    = (const float*)d_in[8];
    const float* g2    = (const float*)d_in[9];
    const float* b2    = (const float*)d_in[10];
    const float* rw1   = (const float*)d_in[11];
    const float* rb1   = (const float*)d_in[12];
    const float* rw2   = (const float*)d_in[13];
    const float* rb2   = (const float*)d_in[14];
    const float* rg    = (const float*)d_in[15];
    const float* rb    = (const float*)d_in[16];
    const float* pemb  = (const float*)d_in[17];
    const float* dw    = (const float*)d_in[18];
    const float* db    = (const float*)d_in[19];
    const float* wgam  = (const float*)d_in[20];
    const float* wbet  = (const float*)d_in[21];
    const float* mw1   = (const float*)d_in[22];
    const float* mb1   = (const float*)d_in[23];
    const float* mw2   = (const float*)d_in[24];
    const float* mb2   = (const float*)d_in[25];
    float* out = (float*)d_out;

    static float *ph=0,*pq=0,*pk=0,*pv=0,*px2=0,*pr=0,*ph3=0,*pt=0,*ppers=0;
    static bool inited = false;
    if (!inited) {
        cudaGetSymbolAddress((void**)&ph,  g_h);
        cudaGetSymbolAddress((void**)&pq,  g_q);
        cudaGetSymbolAddress((void**)&pk,  g_k);
        cudaGetSymbolAddress((void**)&pv,  g_v);
        cudaGetSymbolAddress((void**)&px2, g_x2);
        cudaGetSymbolAddress((void**)&pr,  g_r);
        cudaGetSymbolAddress((void**)&ph3, g_h3);
        cudaGetSymbolAddress((void**)&pt,  g_t);
        cudaGetSymbolAddress((void**)&ppers, g_pers);
        cudaFuncSetAttribute(attn_kernel,
                             cudaFuncAttributeMaxDynamicSharedMemorySize, 114688);
        inited = true;
    }

    const dim3 blk(256);
    auto gemm_grid = [](int M, int N) { return dim3(N/128, M/128); };

    // 1) h = LN1(x)
    ln_kernel<<<M_, blk>>>(x, nullptr, g1, b1, ph);
    // 2) q,k,v
    gemm_kernel<false,false,false><<<gemm_grid(M_,D_), blk>>>(ph, wq, nullptr, nullptr, pq, M_, D_, D_);
    gemm_kernel<false,false,false><<<gemm_grid(M_,D_), blk>>>(ph, wk, nullptr, nullptr, pk, M_, D_, D_);
    gemm_kernel<false,false,false><<<gemm_grid(M_,D_), blk>>>(ph, wv, nullptr, nullptr, pv, M_, D_, D_);
    // 3) attention -> g_t (as [B,S,D])
    attn_kernel<<<dim3(S_/64, H_, B_), blk, 114688>>>(pq, pk, pv, mask, pt);
    // 4) x2 = x + attn_out @ wo
    gemm_kernel<false,false,true><<<gemm_grid(M_,D_), blk>>>(pt, wo, nullptr, x, px2, M_, D_, D_);
    // 5) h2 = LN2(x2)
    ln_kernel<<<M_, blk>>>(px2, nullptr, g2, b2, ph);
    // 6) t = gelu(h2 @ rw1 + rb1)   [M, 2D]
    gemm_kernel<true,true,false><<<gemm_grid(M_,2*D_), blk>>>(ph, rw1, rb1, nullptr, pt, M_, 2*D_, D_);
    // 7) r = t @ rw2 + rb2
    gemm_kernel<false,true,false><<<gemm_grid(M_,D_), blk>>>(pt, rw2, rb2, nullptr, pr, M_, D_, 2*D_);
    // 8) h3 = LN(h2 + r)
    ln_kernel<<<M_, blk>>>(ph, pr, rg, rb, ph3);
    // 9) pers vector (includes db)
    pers_kernel<<<D_/256, blk>>>(pemb, trait, dw, db, ppers);
    // 10) dec = h3 @ dw[:D] + pers  -> g_q (reuse)
    gemm_kernel<false,true,false><<<gemm_grid(M_,D_), blk>>>(ph3, dw, ppers, nullptr, pq, M_, D_, D_);
    // 11) h4 = LN(h3 + dec)
    ln_kernel<<<M_, blk>>>(ph3, pq, wgam, wbet, ph);
    // 12) t = gelu(h4 @ mw1 + mb1)   [M, 4D]
    gemm_kernel<true,true,false><<<gemm_grid(M_,4*D_), blk>>>(ph, mw1, mb1, nullptr, pt, M_, 4*D_, D_);
    // 13) out = x2 + t @ mw2 + mb2
    gemm_kernel<false,true,true><<<gemm_grid(M_,D_), blk>>>(pt, mw2, mb2, px2, out, M_, D_, 4*D_);
}

// round 2
// speedup vs baseline: 1.0029x; 1.0029x over previous
#include <cuda_runtime.h>
#include <math.h>

#define B_  2
#define S_  2048
#define D_  2048
#define H_  16
#define HD_ 128
#define M_  (B_*S_)   // 4096 rows

// ---------------- scratch (static device globals; allocation-free) ----------
__device__ float g_h  [(size_t)M_*D_];
__device__ float g_q  [(size_t)M_*D_];
__device__ float g_k  [(size_t)M_*D_];
__device__ float g_v  [(size_t)M_*D_];
__device__ float g_x2 [(size_t)M_*D_];
__device__ float g_r  [(size_t)M_*D_];
__device__ float g_h3 [(size_t)M_*D_];
__device__ float g_t  [(size_t)M_*4*D_];   // big: FFN 2D / MLP 4D intermediates + attn out
__device__ float g_pers[D_];

// ---------------- GEMM: C = [gelu](A @ W + bias) [+ res] --------------------
// A: MxK row-major, W: KxN row-major. M,N % 128 == 0, K % 16 == 0 (true here).
template<bool GELU, bool BIAS, bool RES>
__global__ __launch_bounds__(256)
void gemm_kernel(const float* __restrict__ A, const float* __restrict__ W,
                 const float* __restrict__ bias, const float* __restrict__ res,
                 float* __restrict__ C, int M, int N, int K)
{
    __shared__ float As[16*132];   // transposed A tile, padded stride
    __shared__ float Bs[16*128];
    const int tid = threadIdx.x;
    const int m0 = blockIdx.y * 128, n0 = blockIdx.x * 128;
    const int tm = tid >> 4, tn = tid & 15;

    float acc[8][8];
    #pragma unroll
    for (int i = 0; i < 8; i++)
        #pragma unroll
        for (int j = 0; j < 8; j++) acc[i][j] = 0.f;

    for (int k0 = 0; k0 < K; k0 += 16) {
        #pragma unroll
        for (int li = 0; li < 2; ++li) {
            int v = li*256 + tid;
            int m = v >> 2, kq = (v & 3) * 4;
            float4 a = *(const float4*)&A[(size_t)(m0+m)*K + k0 + kq];
            As[(kq+0)*132+m] = a.x; As[(kq+1)*132+m] = a.y;
            As[(kq+2)*132+m] = a.z; As[(kq+3)*132+m] = a.w;
        }
        #pragma unroll
        for (int li = 0; li < 2; ++li) {
            int v = li*256 + tid;
            int k = v >> 5, nq = (v & 31) * 4;
            *(float4*)&Bs[k*128+nq] = *(const float4*)&W[(size_t)(k0+k)*N + n0 + nq];
        }
        __syncthreads();
        #pragma unroll
        for (int k = 0; k < 16; k++) {
            float a[8], b[8];
            *(float4*)&a[0] = *(float4*)&As[k*132 + tm*8];
            *(float4*)&a[4] = *(float4*)&As[k*132 + tm*8 + 4];
            *(float4*)&b[0] = *(float4*)&Bs[k*128 + tn*8];
            *(float4*)&b[4] = *(float4*)&Bs[k*128 + tn*8 + 4];
            #pragma unroll
            for (int i = 0; i < 8; i++)
                #pragma unroll
                for (int j = 0; j < 8; j++)
                    acc[i][j] = fmaf(a[i], b[j], acc[i][j]);
        }
        __syncthreads();
    }

    float bv[8];
    if (BIAS) {
        *(float4*)&bv[0] = *(const float4*)&bias[n0 + tn*8];
        *(float4*)&bv[4] = *(const float4*)&bias[n0 + tn*8 + 4];
    }
    #pragma unroll
    for (int i = 0; i < 8; i++) {
        size_t off = (size_t)(m0 + tm*8 + i)*N + n0 + tn*8;
        float o[8];
        #pragma unroll
        for (int j = 0; j < 8; j++) {
            float x = acc[i][j];
            if (BIAS) x += bv[j];
            if (GELU) x = 0.5f * x * (1.0f + erff(x * 0.70710678118654752f));
            o[j] = x;
        }
        if (RES) {
            float4 r0 = *(const float4*)&res[off];
            float4 r1 = *(const float4*)&res[off+4];
            o[0]+=r0.x; o[1]+=r0.y; o[2]+=r0.z; o[3]+=r0.w;
            o[4]+=r1.x; o[5]+=r1.y; o[6]+=r1.z; o[7]+=r1.w;
        }
        *(float4*)&C[off]   = make_float4(o[0],o[1],o[2],o[3]);
        *(float4*)&C[off+4] = make_float4(o[4],o[5],o[6],o[7]);
    }
}

// ---------------- LayerNorm: out = LN(A [+ Ad]) * g + b ---------------------
__global__ __launch_bounds__(256)
void ln_kernel(const float* __restrict__ A, const float* __restrict__ Ad,
               const float* __restrict__ g, const float* __restrict__ bb,
               float* __restrict__ out)
{
    const int row = blockIdx.x, t = threadIdx.x;
    const float* a = A + (size_t)row * D_;
    float4 v[2];
    float s = 0.f, ss = 0.f;
    #pragma unroll
    for (int i = 0; i < 2; i++) {
        int idx = (i*256 + t) * 4;
        float4 x = *(const float4*)&a[idx];
        if (Ad) {
            float4 y = *(const float4*)&Ad[(size_t)row*D_ + idx];
            x.x += y.x; x.y += y.y; x.z += y.z; x.w += y.w;
        }
        v[i] = x;
        s  += x.x + x.y + x.z + x.w;
        ss += x.x*x.x + x.y*x.y + x.z*x.z + x.w*x.w;
    }
    #pragma unroll
    for (int off = 16; off; off >>= 1) {
        s  += __shfl_xor_sync(0xffffffffu, s,  off);
        ss += __shfl_xor_sync(0xffffffffu, ss, off);
    }
    __shared__ float sb[8], ssb[8];
    if ((t & 31) == 0) { sb[t>>5] = s; ssb[t>>5] = ss; }
    __syncthreads();
    float st = 0.f, sst = 0.f;
    #pragma unroll
    for (int i = 0; i < 8; i++) { st += sb[i]; sst += ssb[i]; }
    float mean = st * (1.f / D_);
    float var  = sst * (1.f / D_) - mean * mean;
    float rstd = rsqrtf(var + 1e-5f);
    #pragma unroll
    for (int i = 0; i < 2; i++) {
        int idx = (i*256 + t) * 4;
        float4 gg  = *(const float4*)&g[idx];
        float4 bbv = *(const float4*)&bb[idx];
        float4 x = v[i], o;
        o.x = (x.x - mean)*rstd*gg.x + bbv.x;
        o.y = (x.y - mean)*rstd*gg.y + bbv.y;
        o.z = (x.z - mean)*rstd*gg.z + bbv.z;
        o.w = (x.w - mean)*rstd*gg.w + bbv.w;
        *(float4*)&out[(size_t)row*D_ + idx] = o;
    }
}

// ---------------- persona vector: pers[j] = pemb[t]@dw[D:2D, j] + db[j] -----
__global__ __launch_bounds__(256)
void pers_kernel(const float* __restrict__ pemb, const int* __restrict__ trait,
                 const float* __restrict__ dw, const float* __restrict__ db,
                 float* __restrict__ out)
{
    int j = blockIdx.x * 256 + threadIdx.x;
    int t = trait[0];
    const float* pe = pemb + (size_t)t * D_;
    float acc = db[j];
    for (int i = 0; i < D_; ++i)
        acc = fmaf(pe[i], dw[(size_t)(D_ + i) * D_ + j], acc);
    out[j] = acc;
}

// ---------------- flash attention (fp32, online softmax) --------------------
// Q,K,V stored [B,S,D] with head h at cols h*128..h*128+127. O same layout.
// Block: 64 queries x full head. Tiles of 64 keys. 256 threads = 16x16 map,
// each thread owns 4 q-rows x 4 k-cols for scores, 4 q-rows x 8 dims for O.
__global__ __launch_bounds__(256)
void attn_kernel(const float* __restrict__ Q, const float* __restrict__ K,
                 const float* __restrict__ V, const int* __restrict__ mask,
                 float* __restrict__ O)
{
    extern __shared__ float sm[];
    float* Qt = sm;           // [128][64]  (d-major, conflict-free frags)
    float* Kt = sm + 8192;    // [128][64]
    float* Vs = sm + 16384;   // [64][128]
    float* Ps = sm + 24576;   // [64][64]
    const int tid = threadIdx.x;
    const int b = blockIdx.z, h = blockIdx.y;
    const int q0 = blockIdx.x * 64;
    const float scale = 0.088388347648318447f;  // 1/sqrt(128)

    #pragma unroll
    for (int it = 0; it < 8; ++it) {
        int e = (it*256 + tid) * 4;
        int row = e >> 7, d = e & 127;
        float4 qv = *(const float4*)&Q[((size_t)(b*S_ + q0 + row))*D_ + h*HD_ + d];
        Qt[(d+0)*64+row] = qv.x*scale; Qt[(d+1)*64+row] = qv.y*scale;
        Qt[(d+2)*64+row] = qv.z*scale; Qt[(d+3)*64+row] = qv.w*scale;
    }

    const int ty = tid >> 4, tx = tid & 15;
    float m_i[4], l_i[4], acc[4][8];
    #pragma unroll
    for (int i = 0; i < 4; i++) {
        m_i[i] = -1e30f; l_i[i] = 0.f;
        #pragma unroll
        for (int dd = 0; dd < 8; dd++) acc[i][dd] = 0.f;
    }

    for (int k0 = 0; k0 < S_; k0 += 64) {
        __syncthreads();
        #pragma unroll
        for (int it = 0; it < 8; ++it) {
            int e = (it*256 + tid) * 4;
            int row = e >> 7, d = e & 127;
            size_t goff = ((size_t)(b*S_ + k0 + row))*D_ + h*HD_ + d;
            float4 kv = *(const float4*)&K[goff];
            Kt[(d+0)*64+row] = kv.x; Kt[(d+1)*64+row] = kv.y;
            Kt[(d+2)*64+row] = kv.z; Kt[(d+3)*64+row] = kv.w;
            *(float4*)&Vs[row*128 + d] = *(const float4*)&V[goff];
        }
        __syncthreads();

        float s[4][4];
        #pragma unroll
        for (int i = 0; i < 4; i++)
            #pragma unroll
            for (int j = 0; j < 4; j++) s[i][j] = 0.f;
        #pragma unroll 4
        for (int d = 0; d < 128; ++d) {
            float4 qv = *(float4*)&Qt[d*64 + ty*4];
            float4 kv = *(float4*)&Kt[d*64 + tx*4];
            float qa[4] = {qv.x, qv.y, qv.z, qv.w};
            float ka[4] = {kv.x, kv.y, kv.z, kv.w};
            #pragma unroll
            for (int i = 0; i < 4; i++)
                #pragma unroll
                for (int j = 0; j < 4; j++)
                    s[i][j] = fmaf(qa[i], ka[j], s[i][j]);
        }
        // mask (where mask==0 -> -inf before softmax)
        #pragma unroll
        for (int j = 0; j < 4; j++) {
            if (mask[b*S_ + k0 + tx*4 + j] == 0) {
                #pragma unroll
                for (int i = 0; i < 4; i++) s[i][j] = -1e30f;
            }
        }
        // online softmax update
        #pragma unroll
        for (int i = 0; i < 4; i++) {
            float rm = fmaxf(fmaxf(s[i][0], s[i][1]), fmaxf(s[i][2], s[i][3]));
            rm = fmaxf(rm, __shfl_xor_sync(0xffffffffu, rm, 8, 16));
            rm = fmaxf(rm, __shfl_xor_sync(0xffffffffu, rm, 4, 16));
            rm = fmaxf(rm, __shfl_xor_sync(0xffffffffu, rm, 2, 16));
            rm = fmaxf(rm, __shfl_xor_sync(0xffffffffu, rm, 1, 16));
            float m_new = fmaxf(m_i[i], rm);
            float corr  = __expf(m_i[i] - m_new);
            float p[4], rs = 0.f;
            #pragma unroll
            for (int j = 0; j < 4; j++) { p[j] = __expf(s[i][j] - m_new); rs += p[j]; }
            rs += __shfl_xor_sync(0xffffffffu, rs, 8, 16);
            rs += __shfl_xor_sync(0xffffffffu, rs, 4, 16);
            rs += __shfl_xor_sync(0xffffffffu, rs, 2, 16);
            rs += __shfl_xor_sync(0xffffffffu, rs, 1, 16);
            l_i[i] = l_i[i]*corr + rs;
            m_i[i] = m_new;
            #pragma unroll
            for (int dd = 0; dd < 8; dd++) acc[i][dd] *= corr;
            *(float4*)&Ps[(ty*4 + i)*64 + tx*4] = make_float4(p[0], p[1], p[2], p[3]);
        }
        __syncthreads();
        // O += P @ V
        #pragma unroll 4
        for (int j = 0; j < 64; ++j) {
            float4 v0 = *(float4*)&Vs[j*128 + tx*8];
            float4 v1 = *(float4*)&Vs[j*128 + tx*8 + 4];
            float vv[8] = {v0.x, v0.y, v0.z, v0.w, v1.x, v1.y, v1.z, v1.w};
            #pragma unroll
            for (int i = 0; i < 4; i++) {
                float pv = Ps[(ty*4 + i)*64 + j];
                #pragma unroll
                for (int dd = 0; dd < 8; dd++)
                    acc[i][dd] = fmaf(pv, vv[dd], acc[i][dd]);
            }
        }
    }
    #pragma unroll
    for (int i = 0; i < 4; i++) {
        float inv = 1.0f / l_i[i];
        size_t off = ((size_t)(b*S_ + q0 + ty*4 + i))*D_ + h*HD_ + tx*8;
        *(float4*)&O[off]   = make_float4(acc[i][0]*inv, acc[i][1]*inv, acc[i][2]*inv, acc[i][3]*inv);
        *(float4*)&O[off+4] = make_float4(acc[i][4]*inv, acc[i][5]*inv, acc[i][6]*inv, acc[i][7]*inv);
    }
}

// ---------------- launch ----------------------------------------------------
extern "C" void kernel_launch(void* const* d_in, const int* in_sizes, int n_in,
                              void* d_out, int out_size)
{
    const float* x     = (const float*)d_in[0];
    const int*   mask  = (const int*)  d_in[1];
    const int*   trait = (const int*)  d_in[2];
    const float* wq    = (const float*)d_in[3];
    const float* wk    = (const float*)d_in[4];
    const float* wv    = (const float*)d_in[5];
    const float* wo    = (const float*)d_in[6];
    const float* g1    = (const float*)d_in[7];
    const float* b1    = (const float*)d_in[8];
    const float* g2    = (const float*)d_in[9];
    const float* b2    = (const float*)d_in[10];
    const float* rw1   = (const float*)d_in[11];
    const float* rb1   = (const float*)d_in[12];
    const float* rw2   = (const float*)d_in[13];
    const float* rb2   = (const float*)d_in[14];
    const float* rg    = (const float*)d_in[15];
    const float* rb    = (const float*)d_in[16];
    const float* pemb  = (const float*)d_in[17];
    const float* dw    = (const float*)d_in[18];
    const float* db    = (const float*)d_in[19];
    const float* wgam  = (const float*)d_in[20];
    const float* wbet  = (const float*)d_in[21];
    const float* mw1   = (const float*)d_in[22];
    const float* mb1   = (const float*)d_in[23];
    const float* mw2   = (const float*)d_in[24];
    const float* mb2   = (const float*)d_in[25];
    float* out = (float*)d_out;

    static float *ph=0,*pq=0,*pk=0,*pv=0,*px2=0,*pr=0,*ph3=0,*pt=0,*ppers=0;
    static bool inited = false;
    if (!inited) {
        cudaGetSymbolAddress((void**)&ph,  g_h);
        cudaGetSymbolAddress((void**)&pq,  g_q);
        cudaGetSymbolAddress((void**)&pk,  g_k);
        cudaGetSymbolAddress((void**)&pv,  g_v);
        cudaGetSymbolAddress((void**)&px2, g_x2);
        cudaGetSymbolAddress((void**)&pr,  g_r);
        cudaGetSymbolAddress((void**)&ph3, g_h3);
        cudaGetSymbolAddress((void**)&pt,  g_t);
        cudaGetSymbolAddress((void**)&ppers, g_pers);
        cudaFuncSetAttribute(attn_kernel,
                             cudaFuncAttributeMaxDynamicSharedMemorySize, 114688);
        inited = true;
    }

    const dim3 blk(256);
    auto gemm_grid = [](int M, int N) { return dim3(N/128, M/128); };

    // 1) h = LN1(x)
    ln_kernel<<<M_, blk>>>(x, nullptr, g1, b1, ph);
    // 2) q,k,v
    gemm_kernel<false,false,false><<<gemm_grid(M_,D_), blk>>>(ph, wq, nullptr, nullptr, pq, M_, D_, D_);
    gemm_kernel<false,false,false><<<gemm_grid(M_,D_), blk>>>(ph, wk, nullptr, nullptr, pk, M_, D_, D_);
    gemm_kernel<false,false,false><<<gemm_grid(M_,D_), blk>>>(ph, wv, nullptr, nullptr, pv, M_, D_, D_);
    // 3) attention -> g_t (as [B,S,D])
    attn_kernel<<<dim3(S_/64, H_, B_), blk, 114688>>>(pq, pk, pv, mask, pt);
    // 4) x2 = x + attn_out @ wo
    gemm_kernel<false,false,true><<<gemm_grid(M_,D_), blk>>>(pt, wo, nullptr, x, px2, M_, D_, D_);
    // 5) h2 = LN2(x2)
    ln_kernel<<<M_, blk>>>(px2, nullptr, g2, b2, ph);
    // 6) t = gelu(h2 @ rw1 + rb1)   [M, 2D]
    gemm_kernel<true,true,false><<<gemm_grid(M_,2*D_), blk>>>(ph, rw1, rb1, nullptr, pt, M_, 2*D_, D_);
    // 7) r = t @ rw2 + rb2
    gemm_kernel<false,true,false><<<gemm_grid(M_,D_), blk>>>(pt, rw2, rb2, nullptr, pr, M_, D_, 2*D_);
    // 8) h3 = LN(h2 + r)
    ln_kernel<<<M_, blk>>>(ph, pr, rg, rb, ph3);
    // 9) pers vector (includes db)
    pers_kernel<<<D_/256, blk>>>(pemb, trait, dw, db, ppers);
    // 10) dec = h3 @ dw[:D] + pers  -> g_q (reuse)
    gemm_kernel<false,true,false><<<gemm_grid(M_,D_), blk>>>(ph3, dw, ppers, nullptr, pq, M_, D_, D_);
    // 11) h4 = LN(h3 + dec)
    ln_kernel<<<M_, blk>>>(ph3, pq, wgam, wbet, ph);
    // 12) t = gelu(h4 @ mw1 + mb1)   [M, 4D]
    gemm_kernel<true,true,false><<<gemm_grid(M_,4*D_), blk>>>(ph, mw1, mb1, nullptr, pt, M_, 4*D_, D_);
    // 13) out = x2 + t @ mw2 + mb2
    gemm_kernel<false,true,true><<<gemm_grid(M_,D_), blk>>>(pt, mw2, mb2, px2, out, M_, D_, 4*D_);
}

// round 4
// speedup vs baseline: 1.7176x; 1.7127x over previous
#include <cuda_runtime.h>
#include <cuda_bf16.h>
#include <math.h>
#include <stdint.h>

#define B_  2
#define S_  2048
#define D_  2048
#define H_  16
#define HD_ 128
#define M_  (B_*S_)   // 4096 rows

// ---------------- scratch (static device globals; allocation-free) ----------
__device__ __align__(128) float g_qkv[(size_t)M_*3*D_];   // [M][6144] q|k|v
__device__ __align__(128) float g_x2 [(size_t)M_*D_];
__device__ __align__(128) float g_r  [(size_t)M_*D_];
__device__ __align__(128) float g_h2 [(size_t)M_*D_];
__device__ __align__(128) float g_h3 [(size_t)M_*D_];
__device__ __align__(128) float g_pers[D_];

// bf16 hi/lo activation scratch
__device__ __align__(128) __nv_bfloat16 g_ah[(size_t)M_*D_];
__device__ __align__(128) __nv_bfloat16 g_al[(size_t)M_*D_];
__device__ __align__(128) __nv_bfloat16 g_th[(size_t)M_*4*D_];
__device__ __align__(128) __nv_bfloat16 g_tl[(size_t)M_*4*D_];

// bf16 hi/lo transposed weights, packed offsets into one pool: [N,K] row-major
#define OWQ  ((size_t)0)
#define OWK  ((size_t)4194304)
#define OWV  ((size_t)8388608)
#define OWO  ((size_t)12582912)
#define ORW1 ((size_t)16777216)
#define ORW2 ((size_t)25165824)
#define ODW  ((size_t)33554432)
#define OMW1 ((size_t)37748736)
#define OMW2 ((size_t)54525952)
#define WTOT ((size_t)71303168)
__device__ __align__(128) __nv_bfloat16 g_wh[WTOT];
__device__ __align__(128) __nv_bfloat16 g_wl[WTOT];

// ---------------- helpers ----------------------------------------------------
__device__ __forceinline__ void split2(float v, __nv_bfloat16& h, __nv_bfloat16& l) {
    h = __float2bfloat16(v);
    l = __float2bfloat16(v - __bfloat162float(h));
}

// mma.sync m16n8k16 bf16 with fp32 accumulate (base ISA, works on sm_103 target)
#define MMA16816(d, a, b) \
    asm volatile("mma.sync.aligned.m16n8k16.row.col.f32.bf16.bf16.f32 " \
        "{%0,%1,%2,%3}, {%4,%5,%6,%7}, {%8,%9}, {%0,%1,%2,%3};" \
        : "+f"((d)[0]), "+f"((d)[1]), "+f"((d)[2]), "+f"((d)[3]) \
        : "r"((a)[0]), "r"((a)[1]), "r"((a)[2]), "r"((a)[3]), "r"((b)[0]), "r"((b)[1]))

// ---------------- HMMA GEMM ---------------------------------------------------
// C[M,N] = A @ Wt^T : A = Ah+Al [M,K] bf16 row-major, Wt = Bh+Bl [N,K] bf16 row-major.
// 3-pass split: acc += Ah*Bh + Ah*Bl + Al*Bh.
// CTA tile 128x128, 8 warps (4m x 2n), warp tile 32x64, K-chunk 64, single buffer.
#define LDE 72                       // padded row length in bf16 elements (36 words)
#define MAT_E (128*LDE)              // elements per matrix tile
#define TG_SMEM (4*MAT_E*2)          // 73728 bytes

template<bool GELU, bool BIAS, bool RES, bool OUT_BF16>
__global__ __launch_bounds__(256)
void tgemm(const __nv_bfloat16* __restrict__ Ah, const __nv_bfloat16* __restrict__ Al,
           const __nv_bfloat16* __restrict__ Bh, const __nv_bfloat16* __restrict__ Bl,
           const float* __restrict__ bias, const float* __restrict__ res,
           float* __restrict__ Cf, __nv_bfloat16* __restrict__ Ch, __nv_bfloat16* __restrict__ Cl,
           int M, int N, int K)
{
    extern __shared__ __nv_bfloat16 sm[];
    __nv_bfloat16* sAh = sm;
    __nv_bfloat16* sAl = sm + MAT_E;
    __nv_bfloat16* sBh = sm + 2*MAT_E;
    __nv_bfloat16* sBl = sm + 3*MAT_E;

    const int tid  = threadIdx.x;
    const int lane = tid & 31;
    const int warp = tid >> 5;
    const int wm = warp & 3;          // 0..3 (m, 32 rows each)
    const int wn = warp >> 2;         // 0..1 (n, 64 cols each)
    const int m0 = blockIdx.y * 128;
    const int n0 = blockIdx.x * 128;
    const int g  = lane >> 2;         // groupID 0..7
    const int t  = lane & 3;          // thread-in-group

    float acc[2][8][4];
    #pragma unroll
    for (int m = 0; m < 2; m++)
        #pragma unroll
        for (int n = 0; n < 8; n++)
            #pragma unroll
            for (int e = 0; e < 4; e++) acc[m][n][e] = 0.f;

    const int nc = K >> 6;
    for (int c = 0; c < nc; c++) {
        const int k0 = c << 6;
        // ---- load chunk: each matrix 128x64 via uint4 (8 bf16), 4 per thread --
        #pragma unroll
        for (int i = 0; i < 4; i++) {
            int v = i * 256 + tid;
            int r = v >> 3, q = v & 7;
            int so = r * LDE + q * 8;
            size_t ga = (size_t)(m0 + r) * K + k0 + q * 8;
            size_t gb = (size_t)(n0 + r) * K + k0 + q * 8;
            *(uint4*)&sAh[so] = *(const uint4*)&Ah[ga];
            *(uint4*)&sAl[so] = *(const uint4*)&Al[ga];
            *(uint4*)&sBh[so] = *(const uint4*)&Bh[gb];
            *(uint4*)&sBl[so] = *(const uint4*)&Bl[gb];
        }
        __syncthreads();

        #pragma unroll
        for (int kk = 0; kk < 64; kk += 16) {
            uint32_t ah[2][4], al[2][4];
            #pragma unroll
            for (int m = 0; m < 2; m++) {
                int row = wm * 32 + m * 16 + g;
                int base = row * LDE + kk + t * 2;
                ah[m][0] = *(uint32_t*)&sAh[base];
                ah[m][1] = *(uint32_t*)&sAh[base + 8*LDE];
                ah[m][2] = *(uint32_t*)&sAh[base + 8];
                ah[m][3] = *(uint32_t*)&sAh[base + 8*LDE + 8];
                al[m][0] = *(uint32_t*)&sAl[base];
                al[m][1] = *(uint32_t*)&sAl[base + 8*LDE];
                al[m][2] = *(uint32_t*)&sAl[base + 8];
                al[m][3] = *(uint32_t*)&sAl[base + 8*LDE + 8];
            }
            #pragma unroll
            for (int n = 0; n < 8; n++) {
                int nrow = wn * 64 + n * 8 + g;
                int nb = nrow * LDE + kk + t * 2;
                uint32_t bh[2], bl[2];
                bh[0] = *(uint32_t*)&sBh[nb];
                bh[1] = *(uint32_t*)&sBh[nb + 8];
                bl[0] = *(uint32_t*)&sBl[nb];
                bl[1] = *(uint32_t*)&sBl[nb + 8];
                #pragma unroll
                for (int m = 0; m < 2; m++) {
                    MMA16816(acc[m][n], ah[m], bh);
                    MMA16816(acc[m][n], ah[m], bl);
                    MMA16816(acc[m][n], al[m], bh);
                }
            }
        }
        __syncthreads();
    }

    // ---- epilogue ----
    #pragma unroll
    for (int m = 0; m < 2; m++) {
        #pragma unroll
        for (int n = 0; n < 8; n++) {
            int col = n0 + wn * 64 + n * 8 + t * 2;
            #pragma unroll
            for (int half = 0; half < 2; half++) {
                int row = m0 + wm * 32 + m * 16 + g + half * 8;
                float v0 = acc[m][n][half * 2 + 0];
                float v1 = acc[m][n][half * 2 + 1];
                if (BIAS) { v0 += bias[col]; v1 += bias[col + 1]; }
                if (GELU) {
                    v0 = 0.5f * v0 * (1.0f + erff(v0 * 0.70710678118654752f));
                    v1 = 0.5f * v1 * (1.0f + erff(v1 * 0.70710678118654752f));
                }
                size_t off = (size_t)row * N + col;
                if (RES) {
                    float2 r2 = *(const float2*)&res[off];
                    v0 += r2.x; v1 += r2.y;
                }
                if (OUT_BF16) {
                    __nv_bfloat16 h0, l0, h1, l1;
                    split2(v0, h0, l0); split2(v1, h1, l1);
                    __nv_bfloat162 hp, lp;
                    hp.x = h0; hp.y = h1; lp.x = l0; lp.y = l1;
                    *(__nv_bfloat162*)&Ch[off] = hp;
                    *(__nv_bfloat162*)&Cl[off] = lp;
                } else {
                    *(float2*)&Cf[off] = make_float2(v0, v1);
                }
            }
        }
    }
}

// ---------------- transpose + bf16 split: W[K,N] -> Th/Tl[N,K] --------------
__global__ __launch_bounds__(256)
void transpose_split(const float* __restrict__ W, int K, int N,
                     __nv_bfloat16* __restrict__ Th, __nv_bfloat16* __restrict__ Tl)
{
    __shared__ float tile[32][33];
    const int tx = threadIdx.x, ty = threadIdx.y;
    const int n0 = blockIdx.x * 32, k0 = blockIdx.y * 32;
    #pragma unroll
    for (int i = 0; i < 4; i++)
        tile[ty + 8*i][tx] = W[(size_t)(k0 + ty + 8*i) * N + n0 + tx];
    __syncthreads();
    #pragma unroll
    for (int i = 0; i < 4; i++) {
        float v = tile[tx][ty + 8*i];
        __nv_bfloat16 h, l; split2(v, h, l);
        size_t o = (size_t)(n0 + ty + 8*i) * K + k0 + tx;
        Th[o] = h; Tl[o] = l;
    }
}

// ---------------- LayerNorm: out = LN(A [+ Ad]) * g + b ; + bf16 split ------
__global__ __launch_bounds__(256)
void ln_kernel(const float* __restrict__ A, const float* __restrict__ Ad,
               const float* __restrict__ g, const float* __restrict__ bb,
               float* __restrict__ out, __nv_bfloat16* __restrict__ oh,
               __nv_bfloat16* __restrict__ ol)
{
    const int row = blockIdx.x, t = threadIdx.x;
    const float* a = A + (size_t)row * D_;
    float4 v[2];
    float s = 0.f, ss = 0.f;
    #pragma unroll
    for (int i = 0; i < 2; i++) {
        int idx = (i*256 + t) * 4;
        float4 x = *(const float4*)&a[idx];
        if (Ad) {
            float4 y = *(const float4*)&Ad[(size_t)row*D_ + idx];
            x.x += y.x; x.y += y.y; x.z += y.z; x.w += y.w;
        }
        v[i] = x;
        s  += x.x + x.y + x.z + x.w;
        ss += x.x*x.x + x.y*x.y + x.z*x.z + x.w*x.w;
    }
    #pragma unroll
    for (int off = 16; off; off >>= 1) {
        s  += __shfl_xor_sync(0xffffffffu, s,  off);
        ss += __shfl_xor_sync(0xffffffffu, ss, off);
    }
    __shared__ float sb[8], ssb[8];
    if ((t & 31) == 0) { sb[t>>5] = s; ssb[t>>5] = ss; }
    __syncthreads();
    float st = 0.f, sst = 0.f;
    #pragma unroll
    for (int i = 0; i < 8; i++) { st += sb[i]; sst += ssb[i]; }
    float mean = st * (1.f / D_);
    float var  = sst * (1.f / D_) - mean * mean;
    float rstd = rsqrtf(var + 1e-5f);
    #pragma unroll
    for (int i = 0; i < 2; i++) {
        int idx = (i*256 + t) * 4;
        float4 gg  = *(const float4*)&g[idx];
        float4 bbv = *(const float4*)&bb[idx];
        float4 x = v[i], o;
        o.x = (x.x - mean)*rstd*gg.x + bbv.x;
        o.y = (x.y - mean)*rstd*gg.y + bbv.y;
        o.z = (x.z - mean)*rstd*gg.z + bbv.z;
        o.w = (x.w - mean)*rstd*gg.w + bbv.w;
        if (out) *(float4*)&out[(size_t)row*D_ + idx] = o;
        __nv_bfloat16 hb[4], lb[4];
        split2(o.x, hb[0], lb[0]); split2(o.y, hb[1], lb[1]);
        split2(o.z, hb[2], lb[2]); split2(o.w, hb[3], lb[3]);
        *(uint2*)&oh[(size_t)row*D_ + idx] = *(uint2*)hb;
        *(uint2*)&ol[(size_t)row*D_ + idx] = *(uint2*)lb;
    }
}

// ---------------- persona vector: pers[j] = pemb[t]@dw[D:2D, j] + db[j] -----
__global__ __launch_bounds__(256)
void pers_kernel(const float* __restrict__ pemb, const int* __restrict__ trait,
                 const float* __restrict__ dw, const float* __restrict__ db,
                 float* __restrict__ out)
{
    int j = blockIdx.x * 256 + threadIdx.x;
    int t = trait[0];
    const float* pe = pemb + (size_t)t * D_;
    float acc = db[j];
    for (int i = 0; i < D_; ++i)
        acc = fmaf(pe[i], dw[(size_t)(D_ + i) * D_ + j], acc);
    out[j] = acc;
}

// ---------------- flash attention (fp32 SIMT), outputs bf16 split -----------
// QKV packed [M][6144]: q at col h*128, k at 2048+h*128, v at 4096+h*128.
#define LDQKV 6144
__global__ __launch_bounds__(256)
void attn_kernel(const float* __restrict__ QKV, const int* __restrict__ mask,
                 __nv_bfloat16* __restrict__ Oh, __nv_bfloat16* __restrict__ Ol)
{
    extern __shared__ float smf[];
    float* Qt = smf;           // [128][64]
    float* Kt = smf + 8192;    // [128][64]
    float* Vs = smf + 16384;   // [64][128]
    float* Ps = smf + 24576;   // [64][64]
    const int tid = threadIdx.x;
    const int b = blockIdx.z, h = blockIdx.y;
    const int q0 = blockIdx.x * 64;
    const float scale = 0.088388347648318447f;

    #pragma unroll
    for (int it = 0; it < 8; ++it) {
        int e = (it*256 + tid) * 4;
        int row = e >> 7, d = e & 127;
        float4 qv = *(const float4*)&QKV[((size_t)(b*S_ + q0 + row))*LDQKV + h*HD_ + d];
        Qt[(d+0)*64+row] = qv.x*scale; Qt[(d+1)*64+row] = qv.y*scale;
        Qt[(d+2)*64+row] = qv.z*scale; Qt[(d+3)*64+row] = qv.w*scale;
    }

    const int ty = tid >> 4, tx = tid & 15;
    float m_i[4], l_i[4], acc[4][8];
    #pragma unroll
    for (int i = 0; i < 4; i++) {
        m_i[i] = -1e30f; l_i[i] = 0.f;
        #pragma unroll
        for (int dd = 0; dd < 8; dd++) acc[i][dd] = 0.f;
    }

    for (int k0 = 0; k0 < S_; k0 += 64) {
        __syncthreads();
        #pragma unroll
        for (int it = 0; it < 8; ++it) {
            int e = (it*256 + tid) * 4;
            int row = e >> 7, d = e & 127;
            size_t goff = ((size_t)(b*S_ + k0 + row))*LDQKV + h*HD_ + d;
            float4 kv = *(const float4*)&QKV[goff + 2048];
            Kt[(d+0)*64+row] = kv.x; Kt[(d+1)*64+row] = kv.y;
            Kt[(d+2)*64+row] = kv.z; Kt[(d+3)*64+row] = kv.w;
            *(float4*)&Vs[row*128 + d] = *(const float4*)&QKV[goff + 4096];
        }
        __syncthreads();

        float s[4][4];
        #pragma unroll
        for (int i = 0; i < 4; i++)
            #pragma unroll
            for (int j = 0; j < 4; j++) s[i][j] = 0.f;
        #pragma unroll 4
        for (int d = 0; d < 128; ++d) {
            float4 qv = *(float4*)&Qt[d*64 + ty*4];
            float4 kv = *(float4*)&Kt[d*64 + tx*4];
            float qa[4] = {qv.x, qv.y, qv.z, qv.w};
            float ka[4] = {kv.x, kv.y, kv.z, kv.w};
            #pragma unroll
            for (int i = 0; i < 4; i++)
                #pragma unroll
                for (int j = 0; j < 4; j++)
                    s[i][j] = fmaf(qa[i], ka[j], s[i][j]);
        }
        #pragma unroll
        for (int j = 0; j < 4; j++) {
            if (mask[b*S_ + k0 + tx*4 + j] == 0) {
                #pragma unroll
                for (int i = 0; i < 4; i++) s[i][j] = -1e30f;
            }
        }
        #pragma unroll
        for (int i = 0; i < 4; i++) {
            float rm = fmaxf(fmaxf(s[i][0], s[i][1]), fmaxf(s[i][2], s[i][3]));
            rm = fmaxf(rm, __shfl_xor_sync(0xffffffffu, rm, 8, 16));
            rm = fmaxf(rm, __shfl_xor_sync(0xffffffffu, rm, 4, 16));
            rm = fmaxf(rm, __shfl_xor_sync(0xffffffffu, rm, 2, 16));
            rm = fmaxf(rm, __shfl_xor_sync(0xffffffffu, rm, 1, 16));
            float m_new = fmaxf(m_i[i], rm);
            float corr  = __expf(m_i[i] - m_new);
            float p[4], rs = 0.f;
            #pragma unroll
            for (int j = 0; j < 4; j++) { p[j] = __expf(s[i][j] - m_new); rs += p[j]; }
            rs += __shfl_xor_sync(0xffffffffu, rs, 8, 16);
            rs += __shfl_xor_sync(0xffffffffu, rs, 4, 16);
            rs += __shfl_xor_sync(0xffffffffu, rs, 2, 16);
            rs += __shfl_xor_sync(0xffffffffu, rs, 1, 16);
            l_i[i] = l_i[i]*corr + rs;
            m_i[i] = m_new;
            #pragma unroll
            for (int dd = 0; dd < 8; dd++) acc[i][dd] *= corr;
            *(float4*)&Ps[(ty*4 + i)*64 + tx*4] = make_float4(p[0], p[1], p[2], p[3]);
        }
        __syncthreads();
        #pragma unroll 4
        for (int j = 0; j < 64; ++j) {
            float4 v0 = *(float4*)&Vs[j*128 + tx*8];
            float4 v1 = *(float4*)&Vs[j*128 + tx*8 + 4];
            float vvv[8] = {v0.x, v0.y, v0.z, v0.w, v1.x, v1.y, v1.z, v1.w};
            #pragma unroll
            for (int i = 0; i < 4; i++) {
                float pv = Ps[(ty*4 + i)*64 + j];
                #pragma unroll
                for (int dd = 0; dd < 8; dd++)
                    acc[i][dd] = fmaf(pv, vvv[dd], acc[i][dd]);
            }
        }
    }
    #pragma unroll
    for (int i = 0; i < 4; i++) {
        float inv = 1.0f / l_i[i];
        size_t off = ((size_t)(b*S_ + q0 + ty*4 + i))*D_ + h*HD_ + tx*8;
        __nv_bfloat16 hb[8], lb[8];
        #pragma unroll
        for (int dd = 0; dd < 8; dd++) split2(acc[i][dd]*inv, hb[dd], lb[dd]);
        *(uint4*)&Oh[off] = *(uint4*)hb;
        *(uint4*)&Ol[off] = *(uint4*)lb;
    }
}

// ---------------- launch ----------------------------------------------------
extern "C" void kernel_launch(void* const* d_in, const int* in_sizes, int n_in,
                              void* d_out, int out_size)
{
    const float* x     = (const float*)d_in[0];
    const int*   mask  = (const int*)  d_in[1];
    const int*   trait = (const int*)  d_in[2];
    const float* wq    = (const float*)d_in[3];
    const float* wk    = (const float*)d_in[4];
    const float* wv    = (const float*)d_in[5];
    const float* wo    = (const float*)d_in[6];
    const float* g1    = (const float*)d_in[7];
    const float* b1    = (const float*)d_in[8];
    const float* g2    = (const float*)d_in[9];
    const float* b2    = (const float*)d_in[10];
    const float* rw1   = (const float*)d_in[11];
    const float* rb1   = (const float*)d_in[12];
    const float* rw2   = (const float*)d_in[13];
    const float* rb2   = (const float*)d_in[14];
    const float* rg    = (const float*)d_in[15];
    const float* rb    = (const float*)d_in[16];
    const float* pemb  = (const float*)d_in[17];
    const float* dw    = (const float*)d_in[18];
    const float* db    = (const float*)d_in[19];
    const float* wgam  = (const float*)d_in[20];
    const float* wbet  = (const float*)d_in[21];
    const float* mw1   = (const float*)d_in[22];
    const float* mb1   = (const float*)d_in[23];
    const float* mw2   = (const float*)d_in[24];
    const float* mb2   = (const float*)d_in[25];
    float* out = (float*)d_out;

    static float *pqkv=0,*px2=0,*pr=0,*ph2=0,*ph3=0,*ppers=0;
    static __nv_bfloat16 *pah=0,*pal=0,*pth=0,*ptl=0,*pwh=0,*pwl=0;
    static bool inited = false;
    if (!inited) {
        cudaGetSymbolAddress((void**)&pqkv, g_qkv);
        cudaGetSymbolAddress((void**)&px2, g_x2);
        cudaGetSymbolAddress((void**)&pr,  g_r);
        cudaGetSymbolAddress((void**)&ph2, g_h2);
        cudaGetSymbolAddress((void**)&ph3, g_h3);
        cudaGetSymbolAddress((void**)&ppers, g_pers);
        cudaGetSymbolAddress((void**)&pah, g_ah);
        cudaGetSymbolAddress((void**)&pal, g_al);
        cudaGetSymbolAddress((void**)&pth, g_th);
        cudaGetSymbolAddress((void**)&ptl, g_tl);
        cudaGetSymbolAddress((void**)&pwh, g_wh);
        cudaGetSymbolAddress((void**)&pwl, g_wl);
        cudaFuncSetAttribute(attn_kernel, cudaFuncAttributeMaxDynamicSharedMemorySize, 114688);
        cudaFuncSetAttribute(tgemm<false,false,false,false>, cudaFuncAttributeMaxDynamicSharedMemorySize, TG_SMEM);
        cudaFuncSetAttribute(tgemm<false,false,true,false>,  cudaFuncAttributeMaxDynamicSharedMemorySize, TG_SMEM);
        cudaFuncSetAttribute(tgemm<true,true,false,true>,    cudaFuncAttributeMaxDynamicSharedMemorySize, TG_SMEM);
        cudaFuncSetAttribute(tgemm<false,true,false,false>,  cudaFuncAttributeMaxDynamicSharedMemorySize, TG_SMEM);
        cudaFuncSetAttribute(tgemm<false,true,true,false>,   cudaFuncAttributeMaxDynamicSharedMemorySize, TG_SMEM);
        inited = true;
    }

    const dim3 blk(256);
    const dim3 tb(32, 8);

    // ---- weight prep: transpose + bf16 split (wq|wk|wv contiguous in pool) ----
    transpose_split<<<dim3(64, 64),  tb>>>(wq,  2048, 2048, pwh+OWQ,  pwl+OWQ);
    transpose_split<<<dim3(64, 64),  tb>>>(wk,  2048, 2048, pwh+OWK,  pwl+OWK);
    transpose_split<<<dim3(64, 64),  tb>>>(wv,  2048, 2048, pwh+OWV,  pwl+OWV);
    transpose_split<<<dim3(64, 64),  tb>>>(wo,  2048, 2048, pwh+OWO,  pwl+OWO);
    transpose_split<<<dim3(128, 64), tb>>>(rw1, 2048, 4096, pwh+ORW1, pwl+ORW1);
    transpose_split<<<dim3(64, 128), tb>>>(rw2, 4096, 2048, pwh+ORW2, pwl+ORW2);
    transpose_split<<<dim3(64, 64),  tb>>>(dw,  2048, 2048, pwh+ODW,  pwl+ODW);
    transpose_split<<<dim3(256, 64), tb>>>(mw1, 2048, 8192, pwh+OMW1, pwl+OMW1);
    transpose_split<<<dim3(64, 256), tb>>>(mw2, 8192, 2048, pwh+OMW2, pwl+OMW2);
    pers_kernel<<<D_/256, blk>>>(pemb, trait, dw, db, ppers);

    // 1) h = LN1(x) -> bf16 split
    ln_kernel<<<M_, blk>>>(x, nullptr, g1, b1, nullptr, pah, pal);
    // 2) qkv = h @ [wq|wk|wv]  (one fused GEMM, N=6144)
    tgemm<false,false,false,false><<<dim3(48,32), blk, TG_SMEM>>>(pah,pal, pwh+OWQ,pwl+OWQ, nullptr,nullptr, pqkv,nullptr,nullptr, M_, 3*D_, D_);
    // 3) attention -> bf16 split (reuses pah/pal)
    attn_kernel<<<dim3(S_/64, H_, B_), blk, 114688>>>(pqkv, mask, pah, pal);
    // 4) x2 = x + attn_out @ wo
    tgemm<false,false,true,false><<<dim3(16,32), blk, TG_SMEM>>>(pah,pal, pwh+OWO,pwl+OWO, nullptr,x, px2,nullptr,nullptr, M_, D_, D_);
    // 5) h2 = LN2(x2)
    ln_kernel<<<M_, blk>>>(px2, nullptr, g2, b2, ph2, pah, pal);
    // 6) t = gelu(h2 @ rw1 + rb1)  [M,2D] -> bf16 split
    tgemm<true,true,false,true><<<dim3(32,32), blk, TG_SMEM>>>(pah,pal, pwh+ORW1,pwl+ORW1, rb1,nullptr, nullptr,pth,ptl, M_, 2*D_, D_);
    // 7) r = t @ rw2 + rb2
    tgemm<false,true,false,false><<<dim3(16,32), blk, TG_SMEM>>>(pth,ptl, pwh+ORW2,pwl+ORW2, rb2,nullptr, pr,nullptr,nullptr, M_, D_, 2*D_);
    // 8) h3 = LN(h2 + r)
    ln_kernel<<<M_, blk>>>(ph2, pr, rg, rb, ph3, pah, pal);
    // 9) dec = h3 @ dw[:D] + pers  (pers includes db)
    tgemm<false,true,false,false><<<dim3(16,32), blk, TG_SMEM>>>(pah,pal, pwh+ODW,pwl+ODW, ppers,nullptr, px2==nullptr?nullptr:pqkv,nullptr,nullptr, M_, D_, D_);
    // 10) h4 = LN(h3 + dec)
    ln_kernel<<<M_, blk>>>(ph3, pqkv, wgam, wbet, nullptr, pah, pal);
    // 11) t = gelu(h4 @ mw1 + mb1)  [M,4D] -> bf16 split
    tgemm<true,true,false,true><<<dim3(64,32), blk, TG_SMEM>>>(pah,pal, pwh+OMW1,pwl+OMW1, mb1,nullptr, nullptr,pth,ptl, M_, 4*D_, D_);
    // 12) out = x2 + t @ mw2 + mb2
    tgemm<false,true,true,false><<<dim3(16,32), blk, TG_SMEM>>>(pth,ptl, pwh+OMW2,pwl+OMW2, mb2,px2, out,nullptr,nullptr, M_, D_, 4*D_);
}

// round 5
// speedup vs baseline: 2.0387x; 1.1869x over previous
#include <cuda_runtime.h>
#include <cuda_bf16.h>
#include <math.h>
#include <stdint.h>

#define B_  2
#define S_  2048
#define D_  2048
#define H_  16
#define HD_ 128
#define M_  (B_*S_)   // 4096 rows

// ---------------- scratch (static device globals; allocation-free) ----------
__device__ __align__(128) float g_qkv[(size_t)M_*3*D_];   // [M][6144] q|k|v
__device__ __align__(128) float g_x2 [(size_t)M_*D_];
__device__ __align__(128) float g_r  [(size_t)M_*D_];
__device__ __align__(128) float g_h2 [(size_t)M_*D_];
__device__ __align__(128) float g_h3 [(size_t)M_*D_];
__device__ __align__(128) float g_pers[D_];

// bf16 hi/lo activation scratch
__device__ __align__(128) __nv_bfloat16 g_ah[(size_t)M_*D_];
__device__ __align__(128) __nv_bfloat16 g_al[(size_t)M_*D_];
__device__ __align__(128) __nv_bfloat16 g_th[(size_t)M_*4*D_];
__device__ __align__(128) __nv_bfloat16 g_tl[(size_t)M_*4*D_];

// bf16 hi/lo transposed weights, packed offsets into one pool: [N,K] row-major
#define OWQ  ((size_t)0)
#define OWK  ((size_t)4194304)
#define OWV  ((size_t)8388608)
#define OWO  ((size_t)12582912)
#define ORW1 ((size_t)16777216)
#define ORW2 ((size_t)25165824)
#define ODW  ((size_t)33554432)
#define OMW1 ((size_t)37748736)
#define OMW2 ((size_t)54525952)
#define WTOT ((size_t)71303168)
__device__ __align__(128) __nv_bfloat16 g_wh[WTOT];
__device__ __align__(128) __nv_bfloat16 g_wl[WTOT];

// ---------------- helpers ----------------------------------------------------
__device__ __forceinline__ void split2(float v, __nv_bfloat16& h, __nv_bfloat16& l) {
    h = __float2bfloat16(v);
    l = __float2bfloat16(v - __bfloat162float(h));
}
__device__ __forceinline__ uint32_t smem_u32(const void* p) {
    uint32_t a;
    asm("{ .reg .u64 t; cvta.to.shared.u64 t, %1; cvt.u32.u64 %0, t; }" : "=r"(a) : "l"(p));
    return a;
}

// mma.sync m16n8k16 bf16 with fp32 accumulate (base ISA)
#define MMA16816(d, a, b) \
    asm volatile("mma.sync.aligned.m16n8k16.row.col.f32.bf16.bf16.f32 " \
        "{%0,%1,%2,%3}, {%4,%5,%6,%7}, {%8,%9}, {%0,%1,%2,%3};" \
        : "+f"((d)[0]), "+f"((d)[1]), "+f"((d)[2]), "+f"((d)[3]) \
        : "r"((a)[0]), "r"((a)[1]), "r"((a)[2]), "r"((a)[3]), "r"((b)[0]), "r"((b)[1]))

#define LDMX4(d, addr) \
    asm volatile("ldmatrix.sync.aligned.m8n8.x4.shared.b16 {%0,%1,%2,%3}, [%4];" \
        : "=r"((d)[0]), "=r"((d)[1]), "=r"((d)[2]), "=r"((d)[3]) : "r"(addr))

__device__ __forceinline__ void cp16(uint32_t dst, const void* src) {
    asm volatile("cp.async.cg.shared.global [%0], [%1], 16;" :: "r"(dst), "l"(src));
}
#define CP_COMMIT() asm volatile("cp.async.commit_group;" ::: "memory")
#define CP_WAIT2()  asm volatile("cp.async.wait_group 2;" ::: "memory")

// ---------------- HMMA GEMM (cp.async 3-stage + ldmatrix) --------------------
// C[M,N] = A @ Wt^T : A = Ah+Al [M,K] bf16 row-major, Wt = Bh+Bl [N,K] bf16 row-major.
// 3-pass split: acc += Ah*Bh + Ah*Bl + Al*Bh.
// CTA tile 128x128, 8 warps (4m x 2n), warp tile 32x64, K-chunk 64, 3-stage pipeline.
#define LDE 72                         // padded row length (bf16 elems)
#define MAT_E (128*LDE)                // 9216 elems per matrix tile
#define STAGE_B (4*MAT_E*2)            // 73728 bytes per stage
#define TG_SMEM (3*STAGE_B)            // 221184 bytes

template<bool GELU, bool BIAS, bool RES, bool OUT_BF16>
__global__ __launch_bounds__(256)
void tgemm(const __nv_bfloat16* __restrict__ Ah, const __nv_bfloat16* __restrict__ Al,
           const __nv_bfloat16* __restrict__ Bh, const __nv_bfloat16* __restrict__ Bl,
           const float* __restrict__ bias, const float* __restrict__ res,
           float* __restrict__ Cf, __nv_bfloat16* __restrict__ Ch, __nv_bfloat16* __restrict__ Cl,
           int M, int N, int K)
{
    extern __shared__ __nv_bfloat16 sm[];
    const int tid  = threadIdx.x;
    const int lane = tid & 31;
    const int warp = tid >> 5;
    const int wm = warp & 3;          // m quadrant (32 rows)
    const int wn = warp >> 2;         // n half (64 cols)
    const int m0 = blockIdx.y * 128;
    const int n0 = blockIdx.x * 128;
    const int g  = lane >> 2;
    const int t  = lane & 3;
    const uint32_t sbase = smem_u32(sm);

    // ldmatrix lane-address components
    const int jq = lane >> 3;         // 0..3 (matrix index within x4)
    const int jr = lane & 7;          // row within 8x8

    float acc[2][8][4];
    #pragma unroll
    for (int m = 0; m < 2; m++)
        #pragma unroll
        for (int n = 0; n < 8; n++)
            #pragma unroll
            for (int e = 0; e < 4; e++) acc[m][n][e] = 0.f;

    auto issue = [&](int c, int buf) {
        const int k0 = c << 6;
        const uint32_t b0 = sbase + (uint32_t)buf * STAGE_B;
        #pragma unroll
        for (int i = 0; i < 4; i++) {
            int v = i * 256 + tid;
            int r = v >> 3, q = v & 7;
            uint32_t so = (uint32_t)(r * LDE + q * 8) * 2;
            size_t ga = (size_t)(m0 + r) * K + k0 + q * 8;
            size_t gb = (size_t)(n0 + r) * K + k0 + q * 8;
            cp16(b0 + so,               Ah + ga);
            cp16(b0 + MAT_E*2 + so,     Al + ga);
            cp16(b0 + 2*MAT_E*2 + so,   Bh + gb);
            cp16(b0 + 3*MAT_E*2 + so,   Bl + gb);
        }
        CP_COMMIT();
    };

    const int nc = K >> 6;             // >= 32 for all our shapes
    issue(0, 0); issue(1, 1); issue(2, 2);

    int buf = 0;
    for (int c = 0; c < nc; c++) {
        CP_WAIT2();
        __syncthreads();
        const uint32_t A_h = sbase + (uint32_t)buf * STAGE_B;
        const uint32_t A_l = A_h + MAT_E*2;
        const uint32_t B_h = A_h + 2*MAT_E*2;
        const uint32_t B_l = A_h + 3*MAT_E*2;

        #pragma unroll
        for (int kk = 0; kk < 64; kk += 16) {
            uint32_t ah[2][4], al[2][4];
            #pragma unroll
            for (int m = 0; m < 2; m++) {
                int row = wm * 32 + m * 16 + (jq & 1) * 8 + jr;
                uint32_t off = (uint32_t)(row * LDE + kk + (jq >> 1) * 8) * 2;
                LDMX4(ah[m], A_h + off);
                LDMX4(al[m], A_l + off);
            }
            #pragma unroll
            for (int np = 0; np < 4; np++) {
                int nrow = wn * 64 + np * 16 + (jq >> 1) * 8 + jr;
                uint32_t boff = (uint32_t)(nrow * LDE + kk + (jq & 1) * 8) * 2;
                uint32_t bh[4], bl[4];
                LDMX4(bh, B_h + boff);
                LDMX4(bl, B_l + boff);
                #pragma unroll
                for (int m = 0; m < 2; m++) {
                    MMA16816(acc[m][2*np],   ah[m], &bh[0]);
                    MMA16816(acc[m][2*np],   ah[m], &bl[0]);
                    MMA16816(acc[m][2*np],   al[m], &bh[0]);
                    MMA16816(acc[m][2*np+1], ah[m], &bh[2]);
                    MMA16816(acc[m][2*np+1], ah[m], &bl[2]);
                    MMA16816(acc[m][2*np+1], al[m], &bh[2]);
                }
            }
        }
        __syncthreads();
        if (c + 3 < nc) issue(c + 3, buf);
        buf = (buf == 2) ? 0 : buf + 1;
    }

    // ---- epilogue ----
    #pragma unroll
    for (int m = 0; m < 2; m++) {
        #pragma unroll
        for (int n = 0; n < 8; n++) {
            int col = n0 + wn * 64 + n * 8 + t * 2;
            #pragma unroll
            for (int half = 0; half < 2; half++) {
                int row = m0 + wm * 32 + m * 16 + g + half * 8;
                float v0 = acc[m][n][half * 2 + 0];
                float v1 = acc[m][n][half * 2 + 1];
                if (BIAS) { v0 += bias[col]; v1 += bias[col + 1]; }
                if (GELU) {
                    v0 = 0.5f * v0 * (1.0f + erff(v0 * 0.70710678118654752f));
                    v1 = 0.5f * v1 * (1.0f + erff(v1 * 0.70710678118654752f));
                }
                size_t off = (size_t)row * N + col;
                if (RES) {
                    float2 r2 = *(const float2*)&res[off];
                    v0 += r2.x; v1 += r2.y;
                }
                if (OUT_BF16) {
                    __nv_bfloat16 h0, l0, h1, l1;
                    split2(v0, h0, l0); split2(v1, h1, l1);
                    __nv_bfloat162 hp, lp;
                    hp.x = h0; hp.y = h1; lp.x = l0; lp.y = l1;
                    *(__nv_bfloat162*)&Ch[off] = hp;
                    *(__nv_bfloat162*)&Cl[off] = lp;
                } else {
                    *(float2*)&Cf[off] = make_float2(v0, v1);
                }
            }
        }
    }
}

// ---------------- transpose + bf16 split: W[K,N] -> Th/Tl[N,K] --------------
__global__ __launch_bounds__(256)
void transpose_split(const float* __restrict__ W, int K, int N,
                     __nv_bfloat16* __restrict__ Th, __nv_bfloat16* __restrict__ Tl)
{
    __shared__ float tile[32][33];
    const int tx = threadIdx.x, ty = threadIdx.y;
    const int n0 = blockIdx.x * 32, k0 = blockIdx.y * 32;
    #pragma unroll
    for (int i = 0; i < 4; i++)
        tile[ty + 8*i][tx] = W[(size_t)(k0 + ty + 8*i) * N + n0 + tx];
    __syncthreads();
    #pragma unroll
    for (int i = 0; i < 4; i++) {
        float v = tile[tx][ty + 8*i];
        __nv_bfloat16 h, l; split2(v, h, l);
        size_t o = (size_t)(n0 + ty + 8*i) * K + k0 + tx;
        Th[o] = h; Tl[o] = l;
    }
}

// ---------------- LayerNorm: out = LN(A [+ Ad]) * g + b ; + bf16 split ------
__global__ __launch_bounds__(256)
void ln_kernel(const float* __restrict__ A, const float* __restrict__ Ad,
               const float* __restrict__ g, const float* __restrict__ bb,
               float* __restrict__ out, __nv_bfloat16* __restrict__ oh,
               __nv_bfloat16* __restrict__ ol)
{
    const int row = blockIdx.x, t = threadIdx.x;
    const float* a = A + (size_t)row * D_;
    float4 v[2];
    float s = 0.f, ss = 0.f;
    #pragma unroll
    for (int i = 0; i < 2; i++) {
        int idx = (i*256 + t) * 4;
        float4 x = *(const float4*)&a[idx];
        if (Ad) {
            float4 y = *(const float4*)&Ad[(size_t)row*D_ + idx];
            x.x += y.x; x.y += y.y; x.z += y.z; x.w += y.w;
        }
        v[i] = x;
        s  += x.x + x.y + x.z + x.w;
        ss += x.x*x.x + x.y*x.y + x.z*x.z + x.w*x.w;
    }
    #pragma unroll
    for (int off = 16; off; off >>= 1) {
        s  += __shfl_xor_sync(0xffffffffu, s,  off);
        ss += __shfl_xor_sync(0xffffffffu, ss, off);
    }
    __shared__ float sb[8], ssb[8];
    if ((t & 31) == 0) { sb[t>>5] = s; ssb[t>>5] = ss; }
    __syncthreads();
    float st = 0.f, sst = 0.f;
    #pragma unroll
    for (int i = 0; i < 8; i++) { st += sb[i]; sst += ssb[i]; }
    float mean = st * (1.f / D_);
    float var  = sst * (1.f / D_) - mean * mean;
    float rstd = rsqrtf(var + 1e-5f);
    #pragma unroll
    for (int i = 0; i < 2; i++) {
        int idx = (i*256 + t) * 4;
        float4 gg  = *(const float4*)&g[idx];
        float4 bbv = *(const float4*)&bb[idx];
        float4 x = v[i], o;
        o.x = (x.x - mean)*rstd*gg.x + bbv.x;
        o.y = (x.y - mean)*rstd*gg.y + bbv.y;
        o.z = (x.z - mean)*rstd*gg.z + bbv.z;
        o.w = (x.w - mean)*rstd*gg.w + bbv.w;
        if (out) *(float4*)&out[(size_t)row*D_ + idx] = o;
        __nv_bfloat16 hb[4], lb[4];
        split2(o.x, hb[0], lb[0]); split2(o.y, hb[1], lb[1]);
        split2(o.z, hb[2], lb[2]); split2(o.w, hb[3], lb[3]);
        *(uint2*)&oh[(size_t)row*D_ + idx] = *(uint2*)hb;
        *(uint2*)&ol[(size_t)row*D_ + idx] = *(uint2*)lb;
    }
}

// ---------------- persona vector: pers[j] = pemb[t]@dw[D:2D, j] + db[j] -----
__global__ __launch_bounds__(256)
void pers_kernel(const float* __restrict__ pemb, const int* __restrict__ trait,
                 const float* __restrict__ dw, const float* __restrict__ db,
                 float* __restrict__ out)
{
    int j = blockIdx.x * 256 + threadIdx.x;
    int t = trait[0];
    const float* pe = pemb + (size_t)t * D_;
    float acc = db[j];
    for (int i = 0; i < D_; ++i)
        acc = fmaf(pe[i], dw[(size_t)(D_ + i) * D_ + j], acc);
    out[j] = acc;
}

// ---------------- flash attention (fp32 SIMT), outputs bf16 split -----------
// QKV packed [M][6144]: q at col h*128, k at 2048+h*128, v at 4096+h*128.
#define LDQKV 6144
__global__ __launch_bounds__(256)
void attn_kernel(const float* __restrict__ QKV, const int* __restrict__ mask,
                 __nv_bfloat16* __restrict__ Oh, __nv_bfloat16* __restrict__ Ol)
{
    extern __shared__ float smf[];
    float* Qt = smf;           // [128][64]
    float* Kt = smf + 8192;    // [128][64]
    float* Vs = smf + 16384;   // [64][128]
    float* Ps = smf + 24576;   // [64][64]
    const int tid = threadIdx.x;
    const int b = blockIdx.z, h = blockIdx.y;
    const int q0 = blockIdx.x * 64;
    const float scale = 0.088388347648318447f;

    #pragma unroll
    for (int it = 0; it < 8; ++it) {
        int e = (it*256 + tid) * 4;
        int row = e >> 7, d = e & 127;
        float4 qv = *(const float4*)&QKV[((size_t)(b*S_ + q0 + row))*LDQKV + h*HD_ + d];
        Qt[(d+0)*64+row] = qv.x*scale; Qt[(d+1)*64+row] = qv.y*scale;
        Qt[(d+2)*64+row] = qv.z*scale; Qt[(d+3)*64+row] = qv.w*scale;
    }

    const int ty = tid >> 4, tx = tid & 15;
    float m_i[4], l_i[4], acc[4][8];
    #pragma unroll
    for (int i = 0; i < 4; i++) {
        m_i[i] = -1e30f; l_i[i] = 0.f;
        #pragma unroll
        for (int dd = 0; dd < 8; dd++) acc[i][dd] = 0.f;
    }

    for (int k0 = 0; k0 < S_; k0 += 64) {
        __syncthreads();
        #pragma unroll
        for (int it = 0; it < 8; ++it) {
            int e = (it*256 + tid) * 4;
            int row = e >> 7, d = e & 127;
            size_t goff = ((size_t)(b*S_ + k0 + row))*LDQKV + h*HD_ + d;
            float4 kv = *(const float4*)&QKV[goff + 2048];
            Kt[(d+0)*64+row] = kv.x; Kt[(d+1)*64+row] = kv.y;
            Kt[(d+2)*64+row] = kv.z; Kt[(d+3)*64+row] = kv.w;
            *(float4*)&Vs[row*128 + d] = *(const float4*)&QKV[goff + 4096];
        }
        __syncthreads();

        float s[4][4];
        #pragma unroll
        for (int i = 0; i < 4; i++)
            #pragma unroll
            for (int j = 0; j < 4; j++) s[i][j] = 0.f;
        #pragma unroll 4
        for (int d = 0; d < 128; ++d) {
            float4 qv = *(float4*)&Qt[d*64 + ty*4];
            float4 kv = *(float4*)&Kt[d*64 + tx*4];
            float qa[4] = {qv.x, qv.y, qv.z, qv.w};
            float ka[4] = {kv.x, kv.y, kv.z, kv.w};
            #pragma unroll
            for (int i = 0; i < 4; i++)
                #pragma unroll
                for (int j = 0; j < 4; j++)
                    s[i][j] = fmaf(qa[i], ka[j], s[i][j]);
        }
        #pragma unroll
        for (int j = 0; j < 4; j++) {
            if (mask[b*S_ + k0 + tx*4 + j] == 0) {
                #pragma unroll
                for (int i = 0; i < 4; i++) s[i][j] = -1e30f;
            }
        }
        #pragma unroll
        for (int i = 0; i < 4; i++) {
            float rm = fmaxf(fmaxf(s[i][0], s[i][1]), fmaxf(s[i][2], s[i][3]));
            rm = fmaxf(rm, __shfl_xor_sync(0xffffffffu, rm, 8, 16));
            rm = fmaxf(rm, __shfl_xor_sync(0xffffffffu, rm, 4, 16));
            rm = fmaxf(rm, __shfl_xor_sync(0xffffffffu, rm, 2, 16));
            rm = fmaxf(rm, __shfl_xor_sync(0xffffffffu, rm, 1, 16));
            float m_new = fmaxf(m_i[i], rm);
            float corr  = __expf(m_i[i] - m_new);
            float p[4], rs = 0.f;
            #pragma unroll
            for (int j = 0; j < 4; j++) { p[j] = __expf(s[i][j] - m_new); rs += p[j]; }
            rs += __shfl_xor_sync(0xffffffffu, rs, 8, 16);
            rs += __shfl_xor_sync(0xffffffffu, rs, 4, 16);
            rs += __shfl_xor_sync(0xffffffffu, rs, 2, 16);
            rs += __shfl_xor_sync(0xffffffffu, rs, 1, 16);
            l_i[i] = l_i[i]*corr + rs;
            m_i[i] = m_new;
            #pragma unroll
            for (int dd = 0; dd < 8; dd++) acc[i][dd] *= corr;
            *(float4*)&Ps[(ty*4 + i)*64 + tx*4] = make_float4(p[0], p[1], p[2], p[3]);
        }
        __syncthreads();
        #pragma unroll 4
        for (int j = 0; j < 64; ++j) {
            float4 v0 = *(float4*)&Vs[j*128 + tx*8];
            float4 v1 = *(float4*)&Vs[j*128 + tx*8 + 4];
            float vvv[8] = {v0.x, v0.y, v0.z, v0.w, v1.x, v1.y, v1.z, v1.w};
            #pragma unroll
            for (int i = 0; i < 4; i++) {
                float pv = Ps[(ty*4 + i)*64 + j];
                #pragma unroll
                for (int dd = 0; dd < 8; dd++)
                    acc[i][dd] = fmaf(pv, vvv[dd], acc[i][dd]);
            }
        }
    }
    #pragma unroll
    for (int i = 0; i < 4; i++) {
        float inv = 1.0f / l_i[i];
        size_t off = ((size_t)(b*S_ + q0 + ty*4 + i))*D_ + h*HD_ + tx*8;
        __nv_bfloat16 hb[8], lb[8];
        #pragma unroll
        for (int dd = 0; dd < 8; dd++) split2(acc[i][dd]*inv, hb[dd], lb[dd]);
        *(uint4*)&Oh[off] = *(uint4*)hb;
        *(uint4*)&Ol[off] = *(uint4*)lb;
    }
}

// ---------------- launch ----------------------------------------------------
extern "C" void kernel_launch(void* const* d_in, const int* in_sizes, int n_in,
                              void* d_out, int out_size)
{
    const float* x     = (const float*)d_in[0];
    const int*   mask  = (const int*)  d_in[1];
    const int*   trait = (const int*)  d_in[2];
    const float* wq    = (const float*)d_in[3];
    const float* wk    = (const float*)d_in[4];
    const float* wv    = (const float*)d_in[5];
    const float* wo    = (const float*)d_in[6];
    const float* g1    = (const float*)d_in[7];
    const float* b1    = (const float*)d_in[8];
    const float* g2    = (const float*)d_in[9];
    const float* b2    = (const float*)d_in[10];
    const float* rw1   = (const float*)d_in[11];
    const float* rb1   = (const float*)d_in[12];
    const float* rw2   = (const float*)d_in[13];
    const float* rb2   = (const float*)d_in[14];
    const float* rg    = (const float*)d_in[15];
    const float* rb    = (const float*)d_in[16];
    const float* pemb  = (const float*)d_in[17];
    const float* dw    = (const float*)d_in[18];
    const float* db    = (const float*)d_in[19];
    const float* wgam  = (const float*)d_in[20];
    const float* wbet  = (const float*)d_in[21];
    const float* mw1   = (const float*)d_in[22];
    const float* mb1   = (const float*)d_in[23];
    const float* mw2   = (const float*)d_in[24];
    const float* mb2   = (const float*)d_in[25];
    float* out = (float*)d_out;

    static float *pqkv=0,*px2=0,*pr=0,*ph2=0,*ph3=0,*ppers=0;
    static __nv_bfloat16 *pah=0,*pal=0,*pth=0,*ptl=0,*pwh=0,*pwl=0;
    static bool inited = false;
    if (!inited) {
        cudaGetSymbolAddress((void**)&pqkv, g_qkv);
        cudaGetSymbolAddress((void**)&px2, g_x2);
        cudaGetSymbolAddress((void**)&pr,  g_r);
        cudaGetSymbolAddress((void**)&ph2, g_h2);
        cudaGetSymbolAddress((void**)&ph3, g_h3);
        cudaGetSymbolAddress((void**)&ppers, g_pers);
        cudaGetSymbolAddress((void**)&pah, g_ah);
        cudaGetSymbolAddress((void**)&pal, g_al);
        cudaGetSymbolAddress((void**)&pth, g_th);
        cudaGetSymbolAddress((void**)&ptl, g_tl);
        cudaGetSymbolAddress((void**)&pwh, g_wh);
        cudaGetSymbolAddress((void**)&pwl, g_wl);
        cudaFuncSetAttribute(attn_kernel, cudaFuncAttributeMaxDynamicSharedMemorySize, 114688);
        cudaFuncSetAttribute(tgemm<false,false,false,false>, cudaFuncAttributeMaxDynamicSharedMemorySize, TG_SMEM);
        cudaFuncSetAttribute(tgemm<false,false,true,false>,  cudaFuncAttributeMaxDynamicSharedMemorySize, TG_SMEM);
        cudaFuncSetAttribute(tgemm<true,true,false,true>,    cudaFuncAttributeMaxDynamicSharedMemorySize, TG_SMEM);
        cudaFuncSetAttribute(tgemm<false,true,false,false>,  cudaFuncAttributeMaxDynamicSharedMemorySize, TG_SMEM);
        cudaFuncSetAttribute(tgemm<false,true,true,false>,   cudaFuncAttributeMaxDynamicSharedMemorySize, TG_SMEM);
        inited = true;
    }

    const dim3 blk(256);
    const dim3 tb(32, 8);

    // ---- weight prep: transpose + bf16 split (wq|wk|wv contiguous in pool) ----
    transpose_split<<<dim3(64, 64),  tb>>>(wq,  2048, 2048, pwh+OWQ,  pwl+OWQ);
    transpose_split<<<dim3(64, 64),  tb>>>(wk,  2048, 2048, pwh+OWK,  pwl+OWK);
    transpose_split<<<dim3(64, 64),  tb>>>(wv,  2048, 2048, pwh+OWV,  pwl+OWV);
    transpose_split<<<dim3(64, 64),  tb>>>(wo,  2048, 2048, pwh+OWO,  pwl+OWO);
    transpose_split<<<dim3(128, 64), tb>>>(rw1, 2048, 4096, pwh+ORW1, pwl+ORW1);
    transpose_split<<<dim3(64, 128), tb>>>(rw2, 4096, 2048, pwh+ORW2, pwl+ORW2);
    transpose_split<<<dim3(64, 64),  tb>>>(dw,  2048, 2048, pwh+ODW,  pwl+ODW);
    transpose_split<<<dim3(256, 64), tb>>>(mw1, 2048, 8192, pwh+OMW1, pwl+OMW1);
    transpose_split<<<dim3(64, 256), tb>>>(mw2, 8192, 2048, pwh+OMW2, pwl+OMW2);
    pers_kernel<<<D_/256, blk>>>(pemb, trait, dw, db, ppers);

    // 1) h = LN1(x) -> bf16 split
    ln_kernel<<<M_, blk>>>(x, nullptr, g1, b1, nullptr, pah, pal);
    // 2) qkv = h @ [wq|wk|wv]  (one fused GEMM, N=6144)
    tgemm<false,false,false,false><<<dim3(48,32), blk, TG_SMEM>>>(pah,pal, pwh+OWQ,pwl+OWQ, nullptr,nullptr, pqkv,nullptr,nullptr, M_, 3*D_, D_);
    // 3) attention -> bf16 split (reuses pah/pal)
    attn_kernel<<<dim3(S_/64, H_, B_), blk, 114688>>>(pqkv, mask, pah, pal);
    // 4) x2 = x + attn_out @ wo
    tgemm<false,false,true,false><<<dim3(16,32), blk, TG_SMEM>>>(pah,pal, pwh+OWO,pwl+OWO, nullptr,x, px2,nullptr,nullptr, M_, D_, D_);
    // 5) h2 = LN2(x2)
    ln_kernel<<<M_, blk>>>(px2, nullptr, g2, b2, ph2, pah, pal);
    // 6) t = gelu(h2 @ rw1 + rb1)  [M,2D] -> bf16 split
    tgemm<true,true,false,true><<<dim3(32,32), blk, TG_SMEM>>>(pah,pal, pwh+ORW1,pwl+ORW1, rb1,nullptr, nullptr,pth,ptl, M_, 2*D_, D_);
    // 7) r = t @ rw2 + rb2
    tgemm<false,true,false,false><<<dim3(16,32), blk, TG_SMEM>>>(pth,ptl, pwh+ORW2,pwl+ORW2, rb2,nullptr, pr,nullptr,nullptr, M_, D_, 2*D_);
    // 8) h3 = LN(h2 + r)
    ln_kernel<<<M_, blk>>>(ph2, pr, rg, rb, ph3, pah, pal);
    // 9) dec = h3 @ dw[:D] + pers  (pers includes db)
    tgemm<false,true,false,false><<<dim3(16,32), blk, TG_SMEM>>>(pah,pal, pwh+ODW,pwl+ODW, ppers,nullptr, pqkv,nullptr,nullptr, M_, D_, D_);
    // 10) h4 = LN(h3 + dec)
    ln_kernel<<<M_, blk>>>(ph3, pqkv, wgam, wbet, nullptr, pah, pal);
    // 11) t = gelu(h4 @ mw1 + mb1)  [M,4D] -> bf16 split
    tgemm<true,true,false,true><<<dim3(64,32), blk, TG_SMEM>>>(pah,pal, pwh+OMW1,pwl+OMW1, mb1,nullptr, nullptr,pth,ptl, M_, 4*D_, D_);
    // 12) out = x2 + t @ mw2 + mb2
    tgemm<false,true,true,false><<<dim3(16,32), blk, TG_SMEM>>>(pth,ptl, pwh+OMW2,pwl+OMW2, mb2,px2, out,nullptr,nullptr, M_, D_, 4*D_);
}

// round 6
// speedup vs baseline: 2.6580x; 1.3038x over previous
#include <cuda_runtime.h>
#include <cuda_bf16.h>
#include <math.h>
#include <stdint.h>

#define B_  2
#define S_  2048
#define D_  2048
#define H_  16
#define HD_ 128
#define M_  (B_*S_)   // 4096 rows

// ---------------- scratch (static device globals; allocation-free) ----------
__device__ __align__(128) float g_qkv[(size_t)M_*3*D_];   // [M][6144] q|k|v
__device__ __align__(128) float g_x2 [(size_t)M_*D_];
__device__ __align__(128) float g_r  [(size_t)M_*D_];
__device__ __align__(128) float g_h2 [(size_t)M_*D_];
__device__ __align__(128) float g_h3 [(size_t)M_*D_];
__device__ __align__(128) float g_pers[D_];

// bf16 hi/lo activation scratch
__device__ __align__(128) __nv_bfloat16 g_ah[(size_t)M_*D_];
__device__ __align__(128) __nv_bfloat16 g_al[(size_t)M_*D_];
__device__ __align__(128) __nv_bfloat16 g_th[(size_t)M_*4*D_];
__device__ __align__(128) __nv_bfloat16 g_tl[(size_t)M_*4*D_];

// attention scratch
__device__ __align__(128) __nv_bfloat16 g_qsh[(size_t)M_*D_];
__device__ __align__(128) __nv_bfloat16 g_qsl[(size_t)M_*D_];
__device__ __align__(128) __nv_bfloat16 g_ksh[(size_t)M_*D_];
__device__ __align__(128) __nv_bfloat16 g_ksl[(size_t)M_*D_];
__device__ __align__(128) __nv_bfloat16 g_vth[(size_t)32*HD_*S_];   // [bh][128][2048]
__device__ __align__(128) __nv_bfloat16 g_vtl[(size_t)32*HD_*S_];
__device__ __align__(128) float         g_S  [(size_t)32*S_*S_];    // 537MB scores
__device__ __align__(128) __nv_bfloat16 g_ph [(size_t)32*S_*S_];
__device__ __align__(128) __nv_bfloat16 g_pl [(size_t)32*S_*S_];

// bf16 hi/lo transposed weights, packed offsets into one pool: [N,K] row-major
#define OWQ  ((size_t)0)
#define OWK  ((size_t)4194304)
#define OWV  ((size_t)8388608)
#define OWO  ((size_t)12582912)
#define ORW1 ((size_t)16777216)
#define ORW2 ((size_t)25165824)
#define ODW  ((size_t)33554432)
#define OMW1 ((size_t)37748736)
#define OMW2 ((size_t)54525952)
#define WTOT ((size_t)71303168)
__device__ __align__(128) __nv_bfloat16 g_wh[WTOT];
__device__ __align__(128) __nv_bfloat16 g_wl[WTOT];

// ---------------- helpers ----------------------------------------------------
__device__ __forceinline__ void split2(float v, __nv_bfloat16& h, __nv_bfloat16& l) {
    h = __float2bfloat16(v);
    l = __float2bfloat16(v - __bfloat162float(h));
}
__device__ __forceinline__ uint32_t smem_u32(const void* p) {
    uint32_t a;
    asm("{ .reg .u64 t; cvta.to.shared.u64 t, %1; cvt.u32.u64 %0, t; }" : "=r"(a) : "l"(p));
    return a;
}

#define MMA16816(d, a, b) \
    asm volatile("mma.sync.aligned.m16n8k16.row.col.f32.bf16.bf16.f32 " \
        "{%0,%1,%2,%3}, {%4,%5,%6,%7}, {%8,%9}, {%0,%1,%2,%3};" \
        : "+f"((d)[0]), "+f"((d)[1]), "+f"((d)[2]), "+f"((d)[3]) \
        : "r"((a)[0]), "r"((a)[1]), "r"((a)[2]), "r"((a)[3]), "r"((b)[0]), "r"((b)[1]))

#define LDMX4(d, addr) \
    asm volatile("ldmatrix.sync.aligned.m8n8.x4.shared.b16 {%0,%1,%2,%3}, [%4];" \
        : "=r"((d)[0]), "=r"((d)[1]), "=r"((d)[2]), "=r"((d)[3]) : "r"(addr))

__device__ __forceinline__ void cp16(uint32_t dst, const void* src) {
    asm volatile("cp.async.cg.shared.global [%0], [%1], 16;" :: "r"(dst), "l"(src));
}
#define CP_COMMIT() asm volatile("cp.async.commit_group;" ::: "memory")
#define CP_WAIT2()  asm volatile("cp.async.wait_group 2;" ::: "memory")

// ---------------- HMMA GEMM (batched, cp.async 3-stage + ldmatrix) ----------
// C[M,N] = A @ B^T per batch z: A=Ah+Al [M,K] rows stride lda, B=Bh+Bl [N,K] rows stride ldb.
// Batch offsets: zh=z/zdiv, zl=z%zdiv; off = zh*s1 + zl*s2 (elements).
#define LDE 72
#define MAT_E (128*LDE)
#define STAGE_B (4*MAT_E*2)
#define TG_SMEM (3*STAGE_B)            // 221184 bytes

template<bool GELU, bool BIAS, bool RES, bool OUT_BF16>
__global__ __launch_bounds__(256)
void tbgemm(const __nv_bfloat16* __restrict__ Ah, const __nv_bfloat16* __restrict__ Al,
            const __nv_bfloat16* __restrict__ Bh, const __nv_bfloat16* __restrict__ Bl,
            const float* __restrict__ bias, const float* __restrict__ res,
            float* __restrict__ Cf, __nv_bfloat16* __restrict__ Ch, __nv_bfloat16* __restrict__ Cl,
            int M, int N, int K,
            long long lda, long long ldb, long long ldc, int zdiv,
            long long sA1, long long sA2, long long sB1, long long sB2,
            long long sC1, long long sC2)
{
    extern __shared__ __nv_bfloat16 sm[];
    const int tid  = threadIdx.x;
    const int lane = tid & 31;
    const int warp = tid >> 5;
    const int wm = warp & 3;
    const int wn = warp >> 2;
    const int m0 = blockIdx.y * 128;
    const int n0 = blockIdx.x * 128;
    const int g  = lane >> 2;
    const int t  = lane & 3;
    const uint32_t sbase = smem_u32(sm);
    const int z  = blockIdx.z;
    const int zh = z / zdiv, zl = z % zdiv;
    const size_t Aoff = (size_t)zh * sA1 + (size_t)zl * sA2;
    const size_t Boff = (size_t)zh * sB1 + (size_t)zl * sB2;
    const size_t Coff = (size_t)zh * sC1 + (size_t)zl * sC2;

    const int jq = lane >> 3;
    const int jr = lane & 7;

    float acc[2][8][4];
    #pragma unroll
    for (int m = 0; m < 2; m++)
        #pragma unroll
        for (int n = 0; n < 8; n++)
            #pragma unroll
            for (int e = 0; e < 4; e++) acc[m][n][e] = 0.f;

    auto issue = [&](int c, int buf) {
        const int k0 = c << 6;
        const uint32_t b0 = sbase + (uint32_t)buf * STAGE_B;
        #pragma unroll
        for (int i = 0; i < 4; i++) {
            int v = i * 256 + tid;
            int r = v >> 3, q = v & 7;
            uint32_t so = (uint32_t)(r * LDE + q * 8) * 2;
            size_t ga = Aoff + (size_t)(m0 + r) * lda + k0 + q * 8;
            size_t gb = Boff + (size_t)(n0 + r) * ldb + k0 + q * 8;
            cp16(b0 + so,               Ah + ga);
            cp16(b0 + MAT_E*2 + so,     Al + ga);
            cp16(b0 + 2*MAT_E*2 + so,   Bh + gb);
            cp16(b0 + 3*MAT_E*2 + so,   Bl + gb);
        }
        CP_COMMIT();
    };

    const int nc = K >> 6;
    #pragma unroll
    for (int i = 0; i < 3; i++) {
        if (i < nc) issue(i, i); else CP_COMMIT();
    }

    int buf = 0;
    for (int c = 0; c < nc; c++) {
        CP_WAIT2();
        __syncthreads();
        const uint32_t A_h = sbase + (uint32_t)buf * STAGE_B;
        const uint32_t A_l = A_h + MAT_E*2;
        const uint32_t B_h = A_h + 2*MAT_E*2;
        const uint32_t B_l = A_h + 3*MAT_E*2;

        #pragma unroll
        for (int kk = 0; kk < 64; kk += 16) {
            uint32_t ah[2][4], al[2][4];
            #pragma unroll
            for (int m = 0; m < 2; m++) {
                int row = wm * 32 + m * 16 + (jq & 1) * 8 + jr;
                uint32_t off = (uint32_t)(row * LDE + kk + (jq >> 1) * 8) * 2;
                LDMX4(ah[m], A_h + off);
                LDMX4(al[m], A_l + off);
            }
            #pragma unroll
            for (int np = 0; np < 4; np++) {
                int nrow = wn * 64 + np * 16 + (jq >> 1) * 8 + jr;
                uint32_t boff = (uint32_t)(nrow * LDE + kk + (jq & 1) * 8) * 2;
                uint32_t bh[4], bl[4];
                LDMX4(bh, B_h + boff);
                LDMX4(bl, B_l + boff);
                #pragma unroll
                for (int m = 0; m < 2; m++) {
                    MMA16816(acc[m][2*np],   ah[m], &bh[0]);
                    MMA16816(acc[m][2*np],   ah[m], &bl[0]);
                    MMA16816(acc[m][2*np],   al[m], &bh[0]);
                    MMA16816(acc[m][2*np+1], ah[m], &bh[2]);
                    MMA16816(acc[m][2*np+1], ah[m], &bl[2]);
                    MMA16816(acc[m][2*np+1], al[m], &bh[2]);
                }
            }
        }
        __syncthreads();
        if (c + 3 < nc) issue(c + 3, buf); else CP_COMMIT();
        buf = (buf == 2) ? 0 : buf + 1;
    }

    // ---- epilogue ----
    #pragma unroll
    for (int m = 0; m < 2; m++) {
        #pragma unroll
        for (int n = 0; n < 8; n++) {
            int col = n0 + wn * 64 + n * 8 + t * 2;
            #pragma unroll
            for (int half = 0; half < 2; half++) {
                int row = m0 + wm * 32 + m * 16 + g + half * 8;
                float v0 = acc[m][n][half * 2 + 0];
                float v1 = acc[m][n][half * 2 + 1];
                if (BIAS) { v0 += bias[col]; v1 += bias[col + 1]; }
                if (GELU) {
                    v0 = 0.5f * v0 * (1.0f + erff(v0 * 0.70710678118654752f));
                    v1 = 0.5f * v1 * (1.0f + erff(v1 * 0.70710678118654752f));
                }
                size_t off = Coff + (size_t)row * ldc + col;
                if (RES) {
                    float2 r2 = *(const float2*)&res[off];
                    v0 += r2.x; v1 += r2.y;
                }
                if (OUT_BF16) {
                    __nv_bfloat16 h0, l0, h1, l1;
                    split2(v0, h0, l0); split2(v1, h1, l1);
                    __nv_bfloat162 hp, lp;
                    hp.x = h0; hp.y = h1; lp.x = l0; lp.y = l1;
                    *(__nv_bfloat162*)&Ch[off] = hp;
                    *(__nv_bfloat162*)&Cl[off] = lp;
                } else {
                    *(float2*)&Cf[off] = make_float2(v0, v1);
                }
            }
        }
    }
}

// ---------------- transpose + bf16 split: W[K,N] -> Th/Tl[N,K] --------------
__global__ __launch_bounds__(256)
void transpose_split(const float* __restrict__ W, int K, int N,
                     __nv_bfloat16* __restrict__ Th, __nv_bfloat16* __restrict__ Tl)
{
    __shared__ float tile[32][33];
    const int tx = threadIdx.x, ty = threadIdx.y;
    const int n0 = blockIdx.x * 32, k0 = blockIdx.y * 32;
    #pragma unroll
    for (int i = 0; i < 4; i++)
        tile[ty + 8*i][tx] = W[(size_t)(k0 + ty + 8*i) * N + n0 + tx];
    __syncthreads();
    #pragma unroll
    for (int i = 0; i < 4; i++) {
        float v = tile[tx][ty + 8*i];
        __nv_bfloat16 h, l; split2(v, h, l);
        size_t o = (size_t)(n0 + ty + 8*i) * K + k0 + tx;
        Th[o] = h; Tl[o] = l;
    }
}

// ---------------- qk prep: qkv fp32 -> Q(scaled)/K bf16 splits --------------
__global__ __launch_bounds__(256)
void qk_prep(const float* __restrict__ qkv,
             __nv_bfloat16* __restrict__ qh, __nv_bfloat16* __restrict__ ql,
             __nv_bfloat16* __restrict__ kh, __nv_bfloat16* __restrict__ kl)
{
    const float scale = 0.088388347648318447f;
    size_t e = ((size_t)blockIdx.x * 256 + threadIdx.x) * 4;   // over 4096 x 4096
    int row = (int)(e >> 12);
    int col = (int)(e & 4095);
    float4 v = *(const float4*)&qkv[(size_t)row * 6144 + col];
    __nv_bfloat16 hb[4], lb[4];
    if (col < 2048) {
        split2(v.x*scale, hb[0], lb[0]); split2(v.y*scale, hb[1], lb[1]);
        split2(v.z*scale, hb[2], lb[2]); split2(v.w*scale, hb[3], lb[3]);
        *(uint2*)&qh[(size_t)row*2048 + col] = *(uint2*)hb;
        *(uint2*)&ql[(size_t)row*2048 + col] = *(uint2*)lb;
    } else {
        split2(v.x, hb[0], lb[0]); split2(v.y, hb[1], lb[1]);
        split2(v.z, hb[2], lb[2]); split2(v.w, hb[3], lb[3]);
        *(uint2*)&kh[(size_t)row*2048 + col - 2048] = *(uint2*)hb;
        *(uint2*)&kl[(size_t)row*2048 + col - 2048] = *(uint2*)lb;
    }
}

// ---------------- v prep: transpose V per (b,h) -> [dim][keys] splits -------
__global__ __launch_bounds__(256)
void v_prep(const float* __restrict__ qkv,
            __nv_bfloat16* __restrict__ vth, __nv_bfloat16* __restrict__ vtl)
{
    __shared__ float tile[32][33];
    const int tx = threadIdx.x, ty = threadIdx.y;
    const int z = blockIdx.z, b = z >> 4, h = z & 15;
    const int key0 = blockIdx.x * 32, d0 = blockIdx.y * 32;
    #pragma unroll
    for (int i = 0; i < 4; i++) {
        int key = key0 + ty + 8*i;
        tile[ty + 8*i][tx] = qkv[(size_t)(b*2048 + key)*6144 + 4096 + h*128 + d0 + tx];
    }
    __syncthreads();
    #pragma unroll
    for (int i = 0; i < 4; i++) {
        int d = d0 + ty + 8*i;
        float v = tile[tx][ty + 8*i];
        __nv_bfloat16 hh, ll; split2(v, hh, ll);
        size_t o = ((size_t)z*128 + d)*2048 + key0 + tx;
        vth[o] = hh; vtl[o] = ll;
    }
}

// ---------------- masked softmax over S rows -> P bf16 splits ---------------
__global__ __launch_bounds__(256)
void softmax_kernel(const float* __restrict__ S, const int* __restrict__ mask,
                    __nv_bfloat16* __restrict__ Ph, __nv_bfloat16* __restrict__ Pl)
{
    const int row = blockIdx.x, z = blockIdx.y, b = z >> 4;
    const int t = threadIdx.x;
    const float* s = S + (size_t)z * 4194304 + (size_t)row * 2048;
    float v[8];
    int   mk[8];
    float mx = -3.0e38f;
    #pragma unroll
    for (int i = 0; i < 2; i++) {
        int idx = (i*256 + t) * 4;
        float4 x = *(const float4*)&s[idx];
        int4 mm = *(const int4*)&mask[b*2048 + idx];
        v[i*4+0]=x.x; v[i*4+1]=x.y; v[i*4+2]=x.z; v[i*4+3]=x.w;
        mk[i*4+0]=mm.x; mk[i*4+1]=mm.y; mk[i*4+2]=mm.z; mk[i*4+3]=mm.w;
        #pragma unroll
        for (int j = 0; j < 4; j++)
            if (mk[i*4+j]) mx = fmaxf(mx, v[i*4+j]);
    }
    #pragma unroll
    for (int off = 16; off; off >>= 1) mx = fmaxf(mx, __shfl_xor_sync(0xffffffffu, mx, off));
    __shared__ float smx[8], ssum[8];
    if ((t & 31) == 0) smx[t>>5] = mx;
    __syncthreads();
    float bm = smx[0];
    #pragma unroll
    for (int i = 1; i < 8; i++) bm = fmaxf(bm, smx[i]);
    float e[8], sum = 0.f;
    #pragma unroll
    for (int i = 0; i < 8; i++) {
        e[i] = mk[i] ? __expf(v[i] - bm) : 0.f;
        sum += e[i];
    }
    #pragma unroll
    for (int off = 16; off; off >>= 1) sum += __shfl_xor_sync(0xffffffffu, sum, off);
    if ((t & 31) == 0) ssum[t>>5] = sum;
    __syncthreads();
    float bs = 0.f;
    #pragma unroll
    for (int i = 0; i < 8; i++) bs += ssum[i];
    float inv = 1.0f / bs;
    size_t base = (size_t)z * 4194304 + (size_t)row * 2048;
    #pragma unroll
    for (int i = 0; i < 2; i++) {
        int idx = (i*256 + t) * 4;
        __nv_bfloat16 hb[4], lb[4];
        #pragma unroll
        for (int j = 0; j < 4; j++) split2(e[i*4+j] * inv, hb[j], lb[j]);
        *(uint2*)&Ph[base + idx] = *(uint2*)hb;
        *(uint2*)&Pl[base + idx] = *(uint2*)lb;
    }
}

// ---------------- LayerNorm: out = LN(A [+ Ad]) * g + b ; + bf16 split ------
__global__ __launch_bounds__(256)
void ln_kernel(const float* __restrict__ A, const float* __restrict__ Ad,
               const float* __restrict__ g, const float* __restrict__ bb,
               float* __restrict__ out, __nv_bfloat16* __restrict__ oh,
               __nv_bfloat16* __restrict__ ol)
{
    const int row = blockIdx.x, t = threadIdx.x;
    const float* a = A + (size_t)row * D_;
    float4 v[2];
    float s = 0.f, ss = 0.f;
    #pragma unroll
    for (int i = 0; i < 2; i++) {
        int idx = (i*256 + t) * 4;
        float4 x = *(const float4*)&a[idx];
        if (Ad) {
            float4 y = *(const float4*)&Ad[(size_t)row*D_ + idx];
            x.x += y.x; x.y += y.y; x.z += y.z; x.w += y.w;
        }
        v[i] = x;
        s  += x.x + x.y + x.z + x.w;
        ss += x.x*x.x + x.y*x.y + x.z*x.z + x.w*x.w;
    }
    #pragma unroll
    for (int off = 16; off; off >>= 1) {
        s  += __shfl_xor_sync(0xffffffffu, s,  off);
        ss += __shfl_xor_sync(0xffffffffu, ss, off);
    }
    __shared__ float sb[8], ssb[8];
    if ((t & 31) == 0) { sb[t>>5] = s; ssb[t>>5] = ss; }
    __syncthreads();
    float st = 0.f, sst = 0.f;
    #pragma unroll
    for (int i = 0; i < 8; i++) { st += sb[i]; sst += ssb[i]; }
    float mean = st * (1.f / D_);
    float var  = sst * (1.f / D_) - mean * mean;
    float rstd = rsqrtf(var + 1e-5f);
    #pragma unroll
    for (int i = 0; i < 2; i++) {
        int idx = (i*256 + t) * 4;
        float4 gg  = *(const float4*)&g[idx];
        float4 bbv = *(const float4*)&bb[idx];
        float4 x = v[i], o;
        o.x = (x.x - mean)*rstd*gg.x + bbv.x;
        o.y = (x.y - mean)*rstd*gg.y + bbv.y;
        o.z = (x.z - mean)*rstd*gg.z + bbv.z;
        o.w = (x.w - mean)*rstd*gg.w + bbv.w;
        if (out) *(float4*)&out[(size_t)row*D_ + idx] = o;
        __nv_bfloat16 hb[4], lb[4];
        split2(o.x, hb[0], lb[0]); split2(o.y, hb[1], lb[1]);
        split2(o.z, hb[2], lb[2]); split2(o.w, hb[3], lb[3]);
        *(uint2*)&oh[(size_t)row*D_ + idx] = *(uint2*)hb;
        *(uint2*)&ol[(size_t)row*D_ + idx] = *(uint2*)lb;
    }
}

// ---------------- persona vector: pers[j] = pemb[t]@dw[D:2D, j] + db[j] -----
__global__ __launch_bounds__(256)
void pers_kernel(const float* __restrict__ pemb, const int* __restrict__ trait,
                 const float* __restrict__ dw, const float* __restrict__ db,
                 float* __restrict__ out)
{
    int j = blockIdx.x * 256 + threadIdx.x;
    int t = trait[0];
    const float* pe = pemb + (size_t)t * D_;
    float acc = db[j];
    for (int i = 0; i < D_; ++i)
        acc = fmaf(pe[i], dw[(size_t)(D_ + i) * D_ + j], acc);
    out[j] = acc;
}

// ---------------- launch ----------------------------------------------------
extern "C" void kernel_launch(void* const* d_in, const int* in_sizes, int n_in,
                              void* d_out, int out_size)
{
    const float* x     = (const float*)d_in[0];
    const int*   mask  = (const int*)  d_in[1];
    const int*   trait = (const int*)  d_in[2];
    const float* wq    = (const float*)d_in[3];
    const float* wk    = (const float*)d_in[4];
    const float* wv    = (const float*)d_in[5];
    const float* wo    = (const float*)d_in[6];
    const float* g1    = (const float*)d_in[7];
    const float* b1    = (const float*)d_in[8];
    const float* g2    = (const float*)d_in[9];
    const float* b2    = (const float*)d_in[10];
    const float* rw1   = (const float*)d_in[11];
    const float* rb1   = (const float*)d_in[12];
    const float* rw2   = (const float*)d_in[13];
    const float* rb2   = (const float*)d_in[14];
    const float* rg    = (const float*)d_in[15];
    const float* rb    = (const float*)d_in[16];
    const float* pemb  = (const float*)d_in[17];
    const float* dw    = (const float*)d_in[18];
    const float* db    = (const float*)d_in[19];
    const float* wgam  = (const float*)d_in[20];
    const float* wbet  = (const float*)d_in[21];
    const float* mw1   = (const float*)d_in[22];
    const float* mb1   = (const float*)d_in[23];
    const float* mw2   = (const float*)d_in[24];
    const float* mb2   = (const float*)d_in[25];
    float* out = (float*)d_out;

    static float *pqkv=0,*px2=0,*pr=0,*ph2=0,*ph3=0,*ppers=0,*pS=0;
    static __nv_bfloat16 *pah=0,*pal=0,*pth=0,*ptl=0,*pwh=0,*pwl=0;
    static __nv_bfloat16 *pqsh=0,*pqsl=0,*pksh=0,*pksl=0,*pvth=0,*pvtl=0,*pph=0,*ppl=0;
    static bool inited = false;
    if (!inited) {
        cudaGetSymbolAddress((void**)&pqkv, g_qkv);
        cudaGetSymbolAddress((void**)&px2, g_x2);
        cudaGetSymbolAddress((void**)&pr,  g_r);
        cudaGetSymbolAddress((void**)&ph2, g_h2);
        cudaGetSymbolAddress((void**)&ph3, g_h3);
        cudaGetSymbolAddress((void**)&ppers, g_pers);
        cudaGetSymbolAddress((void**)&pah, g_ah);
        cudaGetSymbolAddress((void**)&pal, g_al);
        cudaGetSymbolAddress((void**)&pth, g_th);
        cudaGetSymbolAddress((void**)&ptl, g_tl);
        cudaGetSymbolAddress((void**)&pwh, g_wh);
        cudaGetSymbolAddress((void**)&pwl, g_wl);
        cudaGetSymbolAddress((void**)&pqsh, g_qsh);
        cudaGetSymbolAddress((void**)&pqsl, g_qsl);
        cudaGetSymbolAddress((void**)&pksh, g_ksh);
        cudaGetSymbolAddress((void**)&pksl, g_ksl);
        cudaGetSymbolAddress((void**)&pvth, g_vth);
        cudaGetSymbolAddress((void**)&pvtl, g_vtl);
        cudaGetSymbolAddress((void**)&pS,  g_S);
        cudaGetSymbolAddress((void**)&pph, g_ph);
        cudaGetSymbolAddress((void**)&ppl, g_pl);
        cudaFuncSetAttribute(tbgemm<false,false,false,false>, cudaFuncAttributeMaxDynamicSharedMemorySize, TG_SMEM);
        cudaFuncSetAttribute(tbgemm<false,false,false,true>,  cudaFuncAttributeMaxDynamicSharedMemorySize, TG_SMEM);
        cudaFuncSetAttribute(tbgemm<false,false,true,false>,  cudaFuncAttributeMaxDynamicSharedMemorySize, TG_SMEM);
        cudaFuncSetAttribute(tbgemm<true,true,false,true>,    cudaFuncAttributeMaxDynamicSharedMemorySize, TG_SMEM);
        cudaFuncSetAttribute(tbgemm<false,true,false,false>,  cudaFuncAttributeMaxDynamicSharedMemorySize, TG_SMEM);
        cudaFuncSetAttribute(tbgemm<false,true,true,false>,   cudaFuncAttributeMaxDynamicSharedMemorySize, TG_SMEM);
        inited = true;
    }

    const dim3 blk(256);
    const dim3 tb(32, 8);
    const long long Z = 0;

    // ---- weight prep ----
    transpose_split<<<dim3(64, 64),  tb>>>(wq,  2048, 2048, pwh+OWQ,  pwl+OWQ);
    transpose_split<<<dim3(64, 64),  tb>>>(wk,  2048, 2048, pwh+OWK,  pwl+OWK);
    transpose_split<<<dim3(64, 64),  tb>>>(wv,  2048, 2048, pwh+OWV,  pwl+OWV);
    transpose_split<<<dim3(64, 64),  tb>>>(wo,  2048, 2048, pwh+OWO,  pwl+OWO);
    transpose_split<<<dim3(128, 64), tb>>>(rw1, 2048, 4096, pwh+ORW1, pwl+ORW1);
    transpose_split<<<dim3(64, 128), tb>>>(rw2, 4096, 2048, pwh+ORW2, pwl+ORW2);
    transpose_split<<<dim3(64, 64),  tb>>>(dw,  2048, 2048, pwh+ODW,  pwl+ODW);
    transpose_split<<<dim3(256, 64), tb>>>(mw1, 2048, 8192, pwh+OMW1, pwl+OMW1);
    transpose_split<<<dim3(64, 256), tb>>>(mw2, 8192, 2048, pwh+OMW2, pwl+OMW2);
    pers_kernel<<<D_/256, blk>>>(pemb, trait, dw, db, ppers);

    // 1) h = LN1(x) -> bf16 split
    ln_kernel<<<M_, blk>>>(x, nullptr, g1, b1, nullptr, pah, pal);
    // 2) qkv = h @ [wq|wk|wv]
    tbgemm<false,false,false,false><<<dim3(48,32,1), blk, TG_SMEM>>>(
        pah,pal, pwh+OWQ,pwl+OWQ, nullptr,nullptr, pqkv,nullptr,nullptr,
        M_, 3*D_, D_, D_, D_, 3*D_, 1, Z,Z,Z,Z,Z,Z);
    // 3) attention prep
    qk_prep<<<16384, blk>>>(pqkv, pqsh, pqsl, pksh, pksl);
    v_prep<<<dim3(64, 4, 32), tb>>>(pqkv, pvth, pvtl);
    // 4) S = Q @ K^T (batched over 32 bh)
    tbgemm<false,false,false,false><<<dim3(16,16,32), blk, TG_SMEM>>>(
        pqsh,pqsl, pksh,pksl, nullptr,nullptr, pS,nullptr,nullptr,
        2048, 2048, 128, 2048, 2048, 2048, 16,
        4194304, 128, 4194304, 128, 67108864, 4194304);
    // 5) P = softmax(S, mask) -> bf16 split
    softmax_kernel<<<dim3(2048, 32), blk>>>(pS, mask, pph, ppl);
    // 6) attn_out = P @ V  (batched) -> pah/pal at [b*2048+s][h*128+d]
    tbgemm<false,false,false,true><<<dim3(1,16,32), blk, TG_SMEM>>>(
        pph,ppl, pvth,pvtl, nullptr,nullptr, nullptr,pah,pal,
        2048, 128, 2048, 2048, 2048, 2048, 16,
        67108864, 4194304, 4194304, 262144, 4194304, 128);
    // 7) x2 = x + attn_out @ wo
    tbgemm<false,false,true,false><<<dim3(16,32,1), blk, TG_SMEM>>>(
        pah,pal, pwh+OWO,pwl+OWO, nullptr,x, px2,nullptr,nullptr,
        M_, D_, D_, D_, D_, D_, 1, Z,Z,Z,Z,Z,Z);
    // 8) h2 = LN2(x2)
    ln_kernel<<<M_, blk>>>(px2, nullptr, g2, b2, ph2, pah, pal);
    // 9) t = gelu(h2 @ rw1 + rb1)
    tbgemm<true,true,false,true><<<dim3(32,32,1), blk, TG_SMEM>>>(
        pah,pal, pwh+ORW1,pwl+ORW1, rb1,nullptr, nullptr,pth,ptl,
        M_, 2*D_, D_, D_, D_, 2*D_, 1, Z,Z,Z,Z,Z,Z);
    // 10) r = t @ rw2 + rb2
    tbgemm<false,true,false,false><<<dim3(16,32,1), blk, TG_SMEM>>>(
        pth,ptl, pwh+ORW2,pwl+ORW2, rb2,nullptr, pr,nullptr,nullptr,
        M_, D_, 2*D_, 2*D_, 2*D_, D_, 1, Z,Z,Z,Z,Z,Z);
    // 11) h3 = LN(h2 + r)
    ln_kernel<<<M_, blk>>>(ph2, pr, rg, rb, ph3, pah, pal);
    // 12) dec = h3 @ dw[:D] + pers
    tbgemm<false,true,false,false><<<dim3(16,32,1), blk, TG_SMEM>>>(
        pah,pal, pwh+ODW,pwl+ODW, ppers,nullptr, pqkv,nullptr,nullptr,
        M_, D_, D_, D_, D_, D_, 1, Z,Z,Z,Z,Z,Z);
    // 13) h4 = LN(h3 + dec)
    ln_kernel<<<M_, blk>>>(ph3, pqkv, wgam, wbet, nullptr, pah, pal);
    // 14) t = gelu(h4 @ mw1 + mb1)
    tbgemm<true,true,false,true><<<dim3(64,32,1), blk, TG_SMEM>>>(
        pah,pal, pwh+OMW1,pwl+OMW1, mb1,nullptr, nullptr,pth,ptl,
        M_, 4*D_, D_, D_, D_, 4*D_, 1, Z,Z,Z,Z,Z,Z);
    // 15) out = x2 + t @ mw2 + mb2
    tbgemm<false,true,true,false><<<dim3(16,32,1), blk, TG_SMEM>>>(
        pth,ptl, pwh+OMW2,pwl+OMW2, mb2,px2, out,nullptr,nullptr,
        M_, D_, 4*D_, 4*D_, 4*D_, D_, 1, Z,Z,Z,Z,Z,Z);
}